// round 12
// baseline (speedup 1.0000x reference)
#include <cuda_runtime.h>
#include <cuda_bf16.h>
#include <float.h>
#include <stdint.h>

#define NN 50000
#define NE 1000000
#define ET (NN + NE)
#define HID 64
#define NG 256
#define SCAN_BLOCKS 49   // ceil(NN/1024)

// ---------------- scratch (static device globals; no runtime allocation) ----
__device__ int   g_cnt[NN];
__device__ int   g_rowptr[NN + 1];
__device__ int   g_cursor[NN];
__device__ int   g_bsum[64];
__device__ int   g_boff[64];
__device__ int   g_csrsrc[ET];
__device__ int   g_batch[NN];
__device__ float g_xl[NN * HID];
__device__ float g_xr[NN * HID];
__device__ float g_res[NN * HID];
__device__ float g_xcur[NN * HID];
__device__ float g_dl[NN];          // 0.6 * (att . xl[row])
__device__ float g_dr[NN];          // 0.6 * (att . xr[row])
__device__ float g_sums[NG * HID];
__device__ float g_cntg[NG];

// ---------------- prep: init (cnt=1 accounts for self-loop) -----------------
__global__ void init_kernel() {
    int i = blockIdx.x * blockDim.x + threadIdx.x;
    if (i < NN) g_cnt[i] = 1;
    if (i < NG * HID) g_sums[i] = 0.f;
    if (i < NG) g_cntg[i] = 0.f;
}

// ---------------- prep: histogram of dst (int4) + batch convert -------------
__global__ void hist_kernel(const int* __restrict__ ei,
                            const int* __restrict__ batch) {
    int i = blockIdx.x * blockDim.x + threadIdx.x;
    if (i < NE / 4) {
        int4 d4 = ((const int4*)(ei + NE))[i];
        atomicAdd(&g_cnt[d4.x], 1);
        atomicAdd(&g_cnt[d4.y], 1);
        atomicAdd(&g_cnt[d4.z], 1);
        atomicAdd(&g_cnt[d4.w], 1);
    }
    if (i < NN) g_batch[i] = batch[i];
}

// ---------------- prep: hierarchical scan ------------------------------------
__global__ void scan1_kernel() {
    int b = blockIdx.x, t = threadIdx.x;
    int idx = b * 1024 + t;
    int lane = t & 31, w = t >> 5;
    int c = (idx < NN) ? g_cnt[idx] : 0;
    int v = c;
#pragma unroll
    for (int o = 1; o < 32; o <<= 1) {
        int u = __shfl_up_sync(0xffffffffu, v, o);
        if (lane >= o) v += u;
    }
    __shared__ int ws[32];
    if (lane == 31) ws[w] = v;
    __syncthreads();
    if (w == 0) {
        int s = ws[lane];
#pragma unroll
        for (int o = 1; o < 32; o <<= 1) {
            int u = __shfl_up_sync(0xffffffffu, s, o);
            if (lane >= o) s += u;
        }
        ws[lane] = s;
    }
    __syncthreads();
    int incl = v + (w > 0 ? ws[w - 1] : 0);
    if (idx < NN) g_cursor[idx] = incl - c;
    if (t == 1023) g_bsum[b] = incl;
}

__global__ void scan2_kernel() {
    __shared__ int sm[64];
    int t = threadIdx.x;
    int v = (t < SCAN_BLOCKS) ? g_bsum[t] : 0;
    sm[t] = v;
    __syncthreads();
    for (int o = 1; o < 64; o <<= 1) {
        int u = (t >= o) ? sm[t - o] : 0;
        __syncthreads();
        sm[t] += u;
        __syncthreads();
    }
    if (t < SCAN_BLOCKS) g_boff[t] = sm[t] - v;
}

__global__ void scan3_kernel() {
    int b = blockIdx.x, t = threadIdx.x;
    int idx = b * 1024 + t;
    if (idx < NN) {
        int r = g_cursor[idx] + g_boff[b];
        g_rowptr[idx] = r;
        g_cursor[idx] = r;
    }
    if (b == 0 && t == 0) g_rowptr[NN] = ET;
}

// ---------------- prep: scatter edges into CSR (grouped by dst) -------------
__global__ void scatter_kernel(const int* __restrict__ ei) {
    int i = blockIdx.x * blockDim.x + threadIdx.x;
    if (i < NE / 4) {
        int4 s4 = ((const int4*)ei)[i];
        int4 d4 = ((const int4*)(ei + NE))[i];
        int p;
        p = atomicAdd(&g_cursor[d4.x], 1); g_csrsrc[p] = s4.x;
        p = atomicAdd(&g_cursor[d4.y], 1); g_csrsrc[p] = s4.y;
        p = atomicAdd(&g_cursor[d4.z], 1); g_csrsrc[p] = s4.z;
        p = atomicAdd(&g_cursor[d4.w], 1); g_csrsrc[p] = s4.w;
    } else {
        int n = i - NE / 4;
        if (n < NN) {
            int p = atomicAdd(&g_cursor[n], 1);
            g_csrsrc[p] = n;
        }
    }
}

// ======================= 3xTF32 mma.sync GEMM ================================
#define APAD 36
#define SM_AH 0
#define SM_AL (128 * APAD)
#define SM_WH (SM_AL + 128 * APAD)
#define SM_WL (SM_WH + 64 * APAD)
#define GEMM_SMEM_WORDS (SM_WL + 64 * APAD)   // 13824 words = 55296 B

__device__ __forceinline__ void split_tf32(float x, uint32_t& hi, uint32_t& lo) {
    asm("cvt.rna.tf32.f32 %0, %1;" : "=r"(hi) : "f"(x));
    float l = x - __uint_as_float(hi);
    asm("cvt.rna.tf32.f32 %0, %1;" : "=r"(lo) : "f"(l));
}

#define MMA_TF32(d, a0, a1, a2, a3, b0, b1)                                   \
    asm volatile(                                                             \
        "mma.sync.aligned.m16n8k8.row.col.f32.tf32.tf32.f32 "                 \
        "{%0,%1,%2,%3}, {%4,%5,%6,%7}, {%8,%9}, {%0,%1,%2,%3};"               \
        : "+f"((d)[0]), "+f"((d)[1]), "+f"((d)[2]), "+f"((d)[3])              \
        : "r"(a0), "r"(a1), "r"(a2), "r"(a3), "r"(b0), "r"(b1))

// z==0 -> g_xl (Wl) + g_dl;  z==1 -> g_xr (Wr) + g_dr;  z==2 -> g_res (Rw)
__global__ __launch_bounds__(256) void gemm_mma_kernel(
    const float* __restrict__ Aext, int use_internal,
    const float* __restrict__ Wl, const float* __restrict__ Wr,
    const float* __restrict__ Rw, const float* __restrict__ att,
    int M, int K) {
    extern __shared__ uint32_t smu[];

    int z = blockIdx.z;
    const float* __restrict__ W = (z == 0) ? Wl : (z == 1) ? Wr : Rw;
    float* __restrict__ C = (z == 0) ? g_xl : (z == 1) ? g_xr : g_res;
    const float* __restrict__ A = use_internal ? (const float*)g_xcur : Aext;

    int tid = threadIdx.x;
    int warp = tid >> 5;
    int lane = tid & 31;
    int gid = lane >> 2;
    int tig = lane & 3;
    int rowBase = blockIdx.x * 128;

    float acc[8][4];
#pragma unroll
    for (int nt = 0; nt < 8; nt++)
#pragma unroll
        for (int j = 0; j < 4; j++) acc[nt][j] = 0.f;

    for (int k0 = 0; k0 < K; k0 += 32) {
#pragma unroll
        for (int p = 0; p < 4; p++) {
            int lin = tid + p * 256;
            int r = lin >> 3;
            int c = lin & 7;
            int row = rowBase + r;
            float4 f = make_float4(0.f, 0.f, 0.f, 0.f);
            if (row < M) f = *(const float4*)&A[(long)row * K + k0 + c * 4];
            uint4 h, l;
            split_tf32(f.x, h.x, l.x);
            split_tf32(f.y, h.y, l.y);
            split_tf32(f.z, h.z, l.z);
            split_tf32(f.w, h.w, l.w);
            *(uint4*)&smu[SM_AH + r * APAD + c * 4] = h;
            *(uint4*)&smu[SM_AL + r * APAD + c * 4] = l;
        }
#pragma unroll
        for (int p = 0; p < 2; p++) {
            int lin = tid + p * 256;
            int n = lin >> 3;
            int c = lin & 7;
            float4 f = *(const float4*)&W[n * K + k0 + c * 4];
            uint4 h, l;
            split_tf32(f.x, h.x, l.x);
            split_tf32(f.y, h.y, l.y);
            split_tf32(f.z, h.z, l.z);
            split_tf32(f.w, h.w, l.w);
            *(uint4*)&smu[SM_WH + n * APAD + c * 4] = h;
            *(uint4*)&smu[SM_WL + n * APAD + c * 4] = l;
        }
        __syncthreads();

#pragma unroll
        for (int kk = 0; kk < 4; kk++) {
            int kb = kk * 8;
            int r0 = warp * 16 + gid;
            uint32_t ah0 = smu[SM_AH + r0 * APAD + kb + tig];
            uint32_t ah1 = smu[SM_AH + (r0 + 8) * APAD + kb + tig];
            uint32_t ah2 = smu[SM_AH + r0 * APAD + kb + tig + 4];
            uint32_t ah3 = smu[SM_AH + (r0 + 8) * APAD + kb + tig + 4];
            uint32_t al0 = smu[SM_AL + r0 * APAD + kb + tig];
            uint32_t al1 = smu[SM_AL + (r0 + 8) * APAD + kb + tig];
            uint32_t al2 = smu[SM_AL + r0 * APAD + kb + tig + 4];
            uint32_t al3 = smu[SM_AL + (r0 + 8) * APAD + kb + tig + 4];
#pragma unroll
            for (int nt = 0; nt < 8; nt++) {
                int bn = nt * 8 + gid;
                uint32_t bh0 = smu[SM_WH + bn * APAD + kb + tig];
                uint32_t bh1 = smu[SM_WH + bn * APAD + kb + tig + 4];
                uint32_t bl0 = smu[SM_WL + bn * APAD + kb + tig];
                uint32_t bl1 = smu[SM_WL + bn * APAD + kb + tig + 4];
                MMA_TF32(acc[nt], ah0, ah1, ah2, ah3, bh0, bh1);
                MMA_TF32(acc[nt], ah0, ah1, ah2, ah3, bl0, bl1);
                MMA_TF32(acc[nt], al0, al1, al2, al3, bh0, bh1);
            }
        }
        __syncthreads();
    }

    int r0 = rowBase + warp * 16 + gid;
    int r1 = r0 + 8;
#pragma unroll
    for (int nt = 0; nt < 8; nt++) {
        int n0 = nt * 8 + 2 * tig;
        if (r0 < M) *(float2*)&C[(long)r0 * HID + n0] = make_float2(acc[nt][0], acc[nt][1]);
        if (r1 < M) *(float2*)&C[(long)r1 * HID + n0] = make_float2(acc[nt][2], acc[nt][3]);
    }

    // fused per-row attention dot for xl / xr: D[row] = 0.6 * (att . C[row])
    if (z < 2) {
        float* __restrict__ D = (z == 0) ? g_dl : g_dr;
        float d0 = 0.f, d1 = 0.f;
#pragma unroll
        for (int nt = 0; nt < 8; nt++) {
            int n0 = nt * 8 + 2 * tig;
            float a0 = att[n0], a1 = att[n0 + 1];
            d0 = fmaf(acc[nt][0], a0, fmaf(acc[nt][1], a1, d0));
            d1 = fmaf(acc[nt][2], a0, fmaf(acc[nt][3], a1, d1));
        }
        d0 += __shfl_xor_sync(0xffffffffu, d0, 1);
        d0 += __shfl_xor_sync(0xffffffffu, d0, 2);
        d1 += __shfl_xor_sync(0xffffffffu, d1, 1);
        d1 += __shfl_xor_sync(0xffffffffu, d1, 2);
        if (tig == 0) {
            if (r0 < M) D[r0] = 0.6f * d0;
            if (r1 < M) D[r1] = 0.6f * d1;
        }
    }
}

// ---------------- GATv2 aggregation: half-warp per node, plain softmax ------
// Factored logit: p = 0.6(att.xl[s] + att.xr[n]) + 0.4*sum_c att_c*|u_c|
// with u = xl[s]+xr[n]. The 0.6-terms are the precomputed g_dl/g_dr; the
// abs-dot uses FFMA |src| modifiers. exp cannot overflow (logits small).
__global__ __launch_bounds__(256) void gat_node_kernel(
    const float* __restrict__ att, const float* __restrict__ bia,
    const float* __restrict__ Rb, int relu_flag, int fuse_pool) {
    int gtid = blockIdx.x * blockDim.x + threadIdx.x;
    int n = gtid >> 4;
    if (n >= NN) return;
    int l = threadIdx.x & 15;
    unsigned mask = 0xFFFFu << (threadIdx.x & 16);
    int c0 = l * 4;

    const float4 xrn = *(const float4*)&g_xr[n * HID + c0];
    float4 av = *(const float4*)&att[c0];
    av.x *= 0.4f; av.y *= 0.4f; av.z *= 0.4f; av.w *= 0.4f;
    const float drn = g_dr[n];   // pre-scaled by 0.6

    float den = 0.f;
    float4 acc = make_float4(0.f, 0.f, 0.f, 0.f);

    int beg = g_rowptr[n], end = g_rowptr[n + 1];
    int last = end - 1;
    int s = g_csrsrc[beg];
    float4 x = *(const float4*)&g_xl[s * HID + c0];
    float dls = g_dl[s];         // pre-scaled by 0.6
    for (int e = beg; e < end; e++) {
        int e1 = e + 1 < last ? e + 1 : last;
        int s1 = g_csrsrc[e1];
        float4 xn = *(const float4*)&g_xl[s1 * HID + c0];
        float dln = g_dl[s1];

        float u0 = x.x + xrn.x;
        float u1 = x.y + xrn.y;
        float u2 = x.z + xrn.z;
        float u3 = x.w + xrn.w;
        // 0.4 * sum att_c |u_c|  (fabs folds into FFMA operand modifier)
        float p = fmaf(av.x, fabsf(u0),
                  fmaf(av.y, fabsf(u1),
                  fmaf(av.z, fabsf(u2), av.w * fabsf(u3))));
        p += __shfl_xor_sync(mask, p, 1);
        p += __shfl_xor_sync(mask, p, 2);
        p += __shfl_xor_sync(mask, p, 4);
        p += __shfl_xor_sync(mask, p, 8);
        p += dls + drn;
        float w = __expf(p);
        den += w;
        acc.x = fmaf(w, x.x, acc.x);
        acc.y = fmaf(w, x.y, acc.y);
        acc.z = fmaf(w, x.z, acc.z);
        acc.w = fmaf(w, x.w, acc.w);
        x = xn;
        dls = dln;
    }
    float inv = 1.f / den;   // self-loop guarantees den > 0
    float4 r4 = *(const float4*)&g_res[n * HID + c0];
    float4 b4 = *(const float4*)&bia[c0];
    float4 rb4 = *(const float4*)&Rb[c0];
    float h0 = acc.x * inv + b4.x + r4.x + rb4.x;
    float h1 = acc.y * inv + b4.y + r4.y + rb4.y;
    float h2 = acc.z * inv + b4.z + r4.z + rb4.z;
    float h3 = acc.w * inv + b4.w + r4.w + rb4.w;
    if (relu_flag) {
        h0 = fmaxf(h0, 0.f); h1 = fmaxf(h1, 0.f);
        h2 = fmaxf(h2, 0.f); h3 = fmaxf(h3, 0.f);
    }
    if (!fuse_pool) {
        *(float4*)&g_xcur[n * HID + c0] = make_float4(h0, h1, h2, h3);
    } else {
        int g = g_batch[n];
        atomicAdd(&g_sums[g * HID + c0 + 0], h0);
        atomicAdd(&g_sums[g * HID + c0 + 1], h1);
        atomicAdd(&g_sums[g * HID + c0 + 2], h2);
        atomicAdd(&g_sums[g * HID + c0 + 3], h3);
        if (l == 0) atomicAdd(&g_cntg[g], 1.f);
    }
}

// ---------------- final: mean pool division + linear head -------------------
__global__ void final_kernel(const float* __restrict__ Wf,
                             const float* __restrict__ bf,
                             float* __restrict__ out) {
    int g = blockIdx.x * blockDim.x + threadIdx.x;
    if (g >= NG) return;
    float acc = 0.f;
#pragma unroll
    for (int c = 0; c < HID; c++) acc += g_sums[g * HID + c] * Wf[c];
    float cnt = fmaxf(g_cntg[g], 1.f);
    out[g] = acc / cnt + bf[0];
}

// --------- static stream/event for prep/GEMM overlap (created pre-baseline) -
namespace {
cudaStream_t s_prep = nullptr;
cudaEvent_t  s_evFork = nullptr, s_evJoin = nullptr;
struct ModulePreload {
    ModulePreload() {
        float z = 0.f;
        (void)cudaMemcpyToSymbol(g_cntg, &z, sizeof(float));
        (void)cudaFuncSetAttribute(gemm_mma_kernel,
                                   cudaFuncAttributeMaxDynamicSharedMemorySize,
                                   GEMM_SMEM_WORDS * 4);
        (void)cudaStreamCreateWithFlags(&s_prep, cudaStreamNonBlocking);
        (void)cudaEventCreateWithFlags(&s_evFork, cudaEventDisableTiming);
        (void)cudaEventCreateWithFlags(&s_evJoin, cudaEventDisableTiming);
        (void)cudaDeviceSynchronize();
    }
};
static ModulePreload s_preload;
}

// ---------------- host driver -----------------------------------------------
extern "C" void kernel_launch(void* const* d_in, const int* in_sizes, int n_in,
                              void* d_out, int out_size) {
    const float* x  = (const float*)d_in[0];
    const int*   ei = (const int*)d_in[1];
    const int*   ba = (const int*)d_in[2];
    const float* Wl0 = (const float*)d_in[3];
    const float* Wr0 = (const float*)d_in[4];
    const float* at0 = (const float*)d_in[5];
    const float* b0  = (const float*)d_in[6];
    const float* Rw0 = (const float*)d_in[7];
    const float* Rb0 = (const float*)d_in[8];
    const float* Wl1 = (const float*)d_in[9];
    const float* Wr1 = (const float*)d_in[10];
    const float* at1 = (const float*)d_in[11];
    const float* b1  = (const float*)d_in[12];
    const float* Rw1 = (const float*)d_in[13];
    const float* Rb1 = (const float*)d_in[14];
    const float* Wl2 = (const float*)d_in[15];
    const float* Wr2 = (const float*)d_in[16];
    const float* at2 = (const float*)d_in[17];
    const float* b2  = (const float*)d_in[18];
    const float* Rw2 = (const float*)d_in[19];
    const float* Rb2 = (const float*)d_in[20];
    const float* Wf  = (const float*)d_in[21];
    const float* bf  = (const float*)d_in[22];
    float* out = (float*)d_out;

    dim3 ggrid((NN + 127) / 128, 1, 3);
    dim3 ngrid((NN * 16 + 255) / 256);
    size_t gsm = GEMM_SMEM_WORDS * 4;

    // fork: CSR build on s_prep, concurrent with layer-0 GEMM on main stream
    cudaEventRecord(s_evFork, 0);
    cudaStreamWaitEvent(s_prep, s_evFork, 0);
    init_kernel<<<(NN + 255) / 256, 256, 0, s_prep>>>();
    hist_kernel<<<(NE / 4 + 255) / 256, 256, 0, s_prep>>>(ei, ba);
    scan1_kernel<<<SCAN_BLOCKS, 1024, 0, s_prep>>>();
    scan2_kernel<<<1, 64, 0, s_prep>>>();
    scan3_kernel<<<SCAN_BLOCKS, 1024, 0, s_prep>>>();
    scatter_kernel<<<(NE / 4 + NN + 255) / 256, 256, 0, s_prep>>>(ei);
    cudaEventRecord(s_evJoin, s_prep);

    // layer 0 projections overlap with CSR build
    gemm_mma_kernel<<<ggrid, 256, gsm>>>(x, 0, Wl0, Wr0, Rw0, at0, NN, 128);
    cudaStreamWaitEvent(0, s_evJoin, 0);
    gat_node_kernel<<<ngrid, 256>>>(at0, b0, Rb0, 1, 0);

    // layer 1 (K=64), relu
    gemm_mma_kernel<<<ggrid, 256, gsm>>>(nullptr, 1, Wl1, Wr1, Rw1, at1, NN, 64);
    gat_node_kernel<<<ngrid, 256>>>(at1, b1, Rb1, 1, 0);

    // layer 2 (K=64), no relu, fused mean-pool scatter
    gemm_mma_kernel<<<ggrid, 256, gsm>>>(nullptr, 1, Wl2, Wr2, Rw2, at2, NN, 64);
    gat_node_kernel<<<ngrid, 256>>>(at2, b2, Rb2, 0, 1);

    final_kernel<<<1, 256>>>(Wf, bf, out);
}

// round 13
// speedup vs baseline: 1.0639x; 1.0639x over previous
#include <cuda_runtime.h>
#include <cuda_fp16.h>
#include <float.h>
#include <stdint.h>

#define NN 50000
#define NE 1000000
#define ET (NN + NE)
#define HID 64
#define NG 256
#define SCAN_BLOCKS 49   // ceil(NN/1024)

// ---------------- scratch (static device globals; no runtime allocation) ----
__device__ int    g_cnt[NN];
__device__ int    g_rowptr[NN + 1];
__device__ int    g_cursor[NN];
__device__ int    g_bsum[64];
__device__ int    g_boff[64];
__device__ int    g_csrsrc[ET];
__device__ int    g_batch[NN];
__device__ __half g_xlh[NN * HID];   // xl stored fp16: halves gather bytes
__device__ float  g_xr[NN * HID];
__device__ float  g_res[NN * HID];
__device__ float  g_xcur[NN * HID];
__device__ float  g_sums[NG * HID];
__device__ float  g_cntg[NG];

// ---------------- prep: init (cnt=1 accounts for self-loop) -----------------
__global__ void init_kernel() {
    int i = blockIdx.x * blockDim.x + threadIdx.x;
    if (i < NN) g_cnt[i] = 1;
    if (i < NG * HID) g_sums[i] = 0.f;
    if (i < NG) g_cntg[i] = 0.f;
}

// ---------------- prep: histogram of dst (int4) + batch convert -------------
__global__ void hist_kernel(const int* __restrict__ ei,
                            const int* __restrict__ batch) {
    int i = blockIdx.x * blockDim.x + threadIdx.x;
    if (i < NE / 4) {
        int4 d4 = ((const int4*)(ei + NE))[i];
        atomicAdd(&g_cnt[d4.x], 1);
        atomicAdd(&g_cnt[d4.y], 1);
        atomicAdd(&g_cnt[d4.z], 1);
        atomicAdd(&g_cnt[d4.w], 1);
    }
    if (i < NN) g_batch[i] = batch[i];
}

// ---------------- prep: hierarchical scan ------------------------------------
__global__ void scan1_kernel() {
    int b = blockIdx.x, t = threadIdx.x;
    int idx = b * 1024 + t;
    int lane = t & 31, w = t >> 5;
    int c = (idx < NN) ? g_cnt[idx] : 0;
    int v = c;
#pragma unroll
    for (int o = 1; o < 32; o <<= 1) {
        int u = __shfl_up_sync(0xffffffffu, v, o);
        if (lane >= o) v += u;
    }
    __shared__ int ws[32];
    if (lane == 31) ws[w] = v;
    __syncthreads();
    if (w == 0) {
        int s = ws[lane];
#pragma unroll
        for (int o = 1; o < 32; o <<= 1) {
            int u = __shfl_up_sync(0xffffffffu, s, o);
            if (lane >= o) s += u;
        }
        ws[lane] = s;
    }
    __syncthreads();
    int incl = v + (w > 0 ? ws[w - 1] : 0);
    if (idx < NN) g_cursor[idx] = incl - c;
    if (t == 1023) g_bsum[b] = incl;
}

__global__ void scan2_kernel() {
    __shared__ int sm[64];
    int t = threadIdx.x;
    int v = (t < SCAN_BLOCKS) ? g_bsum[t] : 0;
    sm[t] = v;
    __syncthreads();
    for (int o = 1; o < 64; o <<= 1) {
        int u = (t >= o) ? sm[t - o] : 0;
        __syncthreads();
        sm[t] += u;
        __syncthreads();
    }
    if (t < SCAN_BLOCKS) g_boff[t] = sm[t] - v;
}

__global__ void scan3_kernel() {
    int b = blockIdx.x, t = threadIdx.x;
    int idx = b * 1024 + t;
    if (idx < NN) {
        int r = g_cursor[idx] + g_boff[b];
        g_rowptr[idx] = r;
        g_cursor[idx] = r;
    }
    if (b == 0 && t == 0) g_rowptr[NN] = ET;
}

// ---------------- prep: scatter edges into CSR (grouped by dst) -------------
__global__ void scatter_kernel(const int* __restrict__ ei) {
    int i = blockIdx.x * blockDim.x + threadIdx.x;
    if (i < NE / 4) {
        int4 s4 = ((const int4*)ei)[i];
        int4 d4 = ((const int4*)(ei + NE))[i];
        int p;
        p = atomicAdd(&g_cursor[d4.x], 1); g_csrsrc[p] = s4.x;
        p = atomicAdd(&g_cursor[d4.y], 1); g_csrsrc[p] = s4.y;
        p = atomicAdd(&g_cursor[d4.z], 1); g_csrsrc[p] = s4.z;
        p = atomicAdd(&g_cursor[d4.w], 1); g_csrsrc[p] = s4.w;
    } else {
        int n = i - NE / 4;
        if (n < NN) {
            int p = atomicAdd(&g_cursor[n], 1);
            g_csrsrc[p] = n;
        }
    }
}

// ======================= 3xTF32 mma.sync GEMM ================================
#define APAD 36
#define SM_AH 0
#define SM_AL (128 * APAD)
#define SM_WH (SM_AL + 128 * APAD)
#define SM_WL (SM_WH + 64 * APAD)
#define GEMM_SMEM_WORDS (SM_WL + 64 * APAD)   // 13824 words = 55296 B

__device__ __forceinline__ void split_tf32(float x, uint32_t& hi, uint32_t& lo) {
    asm("cvt.rna.tf32.f32 %0, %1;" : "=r"(hi) : "f"(x));
    float l = x - __uint_as_float(hi);
    asm("cvt.rna.tf32.f32 %0, %1;" : "=r"(lo) : "f"(l));
}

#define MMA_TF32(d, a0, a1, a2, a3, b0, b1)                                   \
    asm volatile(                                                             \
        "mma.sync.aligned.m16n8k8.row.col.f32.tf32.tf32.f32 "                 \
        "{%0,%1,%2,%3}, {%4,%5,%6,%7}, {%8,%9}, {%0,%1,%2,%3};"               \
        : "+f"((d)[0]), "+f"((d)[1]), "+f"((d)[2]), "+f"((d)[3])              \
        : "r"(a0), "r"(a1), "r"(a2), "r"(a3), "r"(b0), "r"(b1))

// z==0 -> g_xlh (Wl, fp16 out); z==1 -> g_xr (Wr); z==2 -> g_res (Rw)
__global__ __launch_bounds__(256) void gemm_mma_kernel(
    const float* __restrict__ Aext, int use_internal,
    const float* __restrict__ Wl, const float* __restrict__ Wr,
    const float* __restrict__ Rw, int M, int K) {
    extern __shared__ uint32_t smu[];

    int z = blockIdx.z;
    const float* __restrict__ W = (z == 0) ? Wl : (z == 1) ? Wr : Rw;
    const float* __restrict__ A = use_internal ? (const float*)g_xcur : Aext;

    int tid = threadIdx.x;
    int warp = tid >> 5;
    int lane = tid & 31;
    int gid = lane >> 2;
    int tig = lane & 3;
    int rowBase = blockIdx.x * 128;

    float acc[8][4];
#pragma unroll
    for (int nt = 0; nt < 8; nt++)
#pragma unroll
        for (int j = 0; j < 4; j++) acc[nt][j] = 0.f;

    for (int k0 = 0; k0 < K; k0 += 32) {
#pragma unroll
        for (int p = 0; p < 4; p++) {
            int lin = tid + p * 256;
            int r = lin >> 3;
            int c = lin & 7;
            int row = rowBase + r;
            float4 f = make_float4(0.f, 0.f, 0.f, 0.f);
            if (row < M) f = *(const float4*)&A[(long)row * K + k0 + c * 4];
            uint4 h, l;
            split_tf32(f.x, h.x, l.x);
            split_tf32(f.y, h.y, l.y);
            split_tf32(f.z, h.z, l.z);
            split_tf32(f.w, h.w, l.w);
            *(uint4*)&smu[SM_AH + r * APAD + c * 4] = h;
            *(uint4*)&smu[SM_AL + r * APAD + c * 4] = l;
        }
#pragma unroll
        for (int p = 0; p < 2; p++) {
            int lin = tid + p * 256;
            int n = lin >> 3;
            int c = lin & 7;
            float4 f = *(const float4*)&W[n * K + k0 + c * 4];
            uint4 h, l;
            split_tf32(f.x, h.x, l.x);
            split_tf32(f.y, h.y, l.y);
            split_tf32(f.z, h.z, l.z);
            split_tf32(f.w, h.w, l.w);
            *(uint4*)&smu[SM_WH + n * APAD + c * 4] = h;
            *(uint4*)&smu[SM_WL + n * APAD + c * 4] = l;
        }
        __syncthreads();

#pragma unroll
        for (int kk = 0; kk < 4; kk++) {
            int kb = kk * 8;
            int r0 = warp * 16 + gid;
            uint32_t ah0 = smu[SM_AH + r0 * APAD + kb + tig];
            uint32_t ah1 = smu[SM_AH + (r0 + 8) * APAD + kb + tig];
            uint32_t ah2 = smu[SM_AH + r0 * APAD + kb + tig + 4];
            uint32_t ah3 = smu[SM_AH + (r0 + 8) * APAD + kb + tig + 4];
            uint32_t al0 = smu[SM_AL + r0 * APAD + kb + tig];
            uint32_t al1 = smu[SM_AL + (r0 + 8) * APAD + kb + tig];
            uint32_t al2 = smu[SM_AL + r0 * APAD + kb + tig + 4];
            uint32_t al3 = smu[SM_AL + (r0 + 8) * APAD + kb + tig + 4];
#pragma unroll
            for (int nt = 0; nt < 8; nt++) {
                int bn = nt * 8 + gid;
                uint32_t bh0 = smu[SM_WH + bn * APAD + kb + tig];
                uint32_t bh1 = smu[SM_WH + bn * APAD + kb + tig + 4];
                uint32_t bl0 = smu[SM_WL + bn * APAD + kb + tig];
                uint32_t bl1 = smu[SM_WL + bn * APAD + kb + tig + 4];
                MMA_TF32(acc[nt], ah0, ah1, ah2, ah3, bh0, bh1);
                MMA_TF32(acc[nt], ah0, ah1, ah2, ah3, bl0, bl1);
                MMA_TF32(acc[nt], al0, al1, al2, al3, bh0, bh1);
            }
        }
        __syncthreads();
    }

    int r0 = rowBase + warp * 16 + gid;
    int r1 = r0 + 8;
    if (z == 0) {
        // xl: write fp16 (half2 per fragment pair)
#pragma unroll
        for (int nt = 0; nt < 8; nt++) {
            int n0 = nt * 8 + 2 * tig;
            if (r0 < M)
                *(__half2*)&g_xlh[(long)r0 * HID + n0] =
                    __floats2half2_rn(acc[nt][0], acc[nt][1]);
            if (r1 < M)
                *(__half2*)&g_xlh[(long)r1 * HID + n0] =
                    __floats2half2_rn(acc[nt][2], acc[nt][3]);
        }
    } else {
        float* __restrict__ C = (z == 1) ? g_xr : g_res;
#pragma unroll
        for (int nt = 0; nt < 8; nt++) {
            int n0 = nt * 8 + 2 * tig;
            if (r0 < M) *(float2*)&C[(long)r0 * HID + n0] = make_float2(acc[nt][0], acc[nt][1]);
            if (r1 < M) *(float2*)&C[(long)r1 * HID + n0] = make_float2(acc[nt][2], acc[nt][3]);
        }
    }
}

// ---------------- GATv2 aggregation: half-warp per node, plain softmax ------
// xl gathered as fp16 (8B/lane = 128B/edge, half the L2 traffic).
// Logits provably small, exp cannot overflow: alpha = exp(p)/sum.
__global__ __launch_bounds__(256) void gat_node_kernel(
    const float* __restrict__ att, const float* __restrict__ bia,
    const float* __restrict__ Rb, int relu_flag, int fuse_pool) {
    int gtid = blockIdx.x * blockDim.x + threadIdx.x;
    int n = gtid >> 4;
    if (n >= NN) return;
    int l = threadIdx.x & 15;
    unsigned mask = 0xFFFFu << (threadIdx.x & 16);
    int c0 = l * 4;

    const float4 xrn = *(const float4*)&g_xr[n * HID + c0];
    const float4 av  = *(const float4*)&att[c0];

    float den = 0.f;
    float4 acc = make_float4(0.f, 0.f, 0.f, 0.f);

    int e = g_rowptr[n], end = g_rowptr[n + 1];
    for (; e < end; e++) {
        int s = g_csrsrc[e];
        uint2 raw = *(const uint2*)&g_xlh[(long)s * HID + c0];
        float2 f01 = __half22float2(*(__half2*)&raw.x);
        float2 f23 = __half22float2(*(__half2*)&raw.y);
        float v0 = f01.x + xrn.x; v0 = fmaxf(v0, 0.2f * v0);
        float v1 = f01.y + xrn.y; v1 = fmaxf(v1, 0.2f * v1);
        float v2 = f23.x + xrn.z; v2 = fmaxf(v2, 0.2f * v2);
        float v3 = f23.y + xrn.w; v3 = fmaxf(v3, 0.2f * v3);
        float p = fmaf(v0, av.x, fmaf(v1, av.y, fmaf(v2, av.z, v3 * av.w)));
        p += __shfl_xor_sync(mask, p, 1);
        p += __shfl_xor_sync(mask, p, 2);
        p += __shfl_xor_sync(mask, p, 4);
        p += __shfl_xor_sync(mask, p, 8);
        float w = __expf(p);
        den += w;
        acc.x = fmaf(w, f01.x, acc.x);
        acc.y = fmaf(w, f01.y, acc.y);
        acc.z = fmaf(w, f23.x, acc.z);
        acc.w = fmaf(w, f23.y, acc.w);
    }
    float inv = 1.f / den;   // self-loop guarantees den > 0
    float4 r4 = *(const float4*)&g_res[n * HID + c0];
    float4 b4 = *(const float4*)&bia[c0];
    float4 rb4 = *(const float4*)&Rb[c0];
    float h0 = acc.x * inv + b4.x + r4.x + rb4.x;
    float h1 = acc.y * inv + b4.y + r4.y + rb4.y;
    float h2 = acc.z * inv + b4.z + r4.z + rb4.z;
    float h3 = acc.w * inv + b4.w + r4.w + rb4.w;
    if (relu_flag) {
        h0 = fmaxf(h0, 0.f); h1 = fmaxf(h1, 0.f);
        h2 = fmaxf(h2, 0.f); h3 = fmaxf(h3, 0.f);
    }
    if (!fuse_pool) {
        *(float4*)&g_xcur[n * HID + c0] = make_float4(h0, h1, h2, h3);
    } else {
        int g = g_batch[n];
        atomicAdd(&g_sums[g * HID + c0 + 0], h0);
        atomicAdd(&g_sums[g * HID + c0 + 1], h1);
        atomicAdd(&g_sums[g * HID + c0 + 2], h2);
        atomicAdd(&g_sums[g * HID + c0 + 3], h3);
        if (l == 0) atomicAdd(&g_cntg[g], 1.f);
    }
}

// ---------------- final: mean pool division + linear head -------------------
__global__ void final_kernel(const float* __restrict__ Wf,
                             const float* __restrict__ bf,
                             float* __restrict__ out) {
    int g = blockIdx.x * blockDim.x + threadIdx.x;
    if (g >= NG) return;
    float acc = 0.f;
#pragma unroll
    for (int c = 0; c < HID; c++) acc += g_sums[g * HID + c] * Wf[c];
    float cnt = fmaxf(g_cntg[g], 1.f);
    out[g] = acc / cnt + bf[0];
}

// --------- static stream/event for prep/GEMM overlap (created pre-baseline) -
namespace {
cudaStream_t s_prep = nullptr;
cudaEvent_t  s_evFork = nullptr, s_evJoin = nullptr;
struct ModulePreload {
    ModulePreload() {
        float z = 0.f;
        (void)cudaMemcpyToSymbol(g_cntg, &z, sizeof(float));
        (void)cudaFuncSetAttribute(gemm_mma_kernel,
                                   cudaFuncAttributeMaxDynamicSharedMemorySize,
                                   GEMM_SMEM_WORDS * 4);
        (void)cudaStreamCreateWithFlags(&s_prep, cudaStreamNonBlocking);
        (void)cudaEventCreateWithFlags(&s_evFork, cudaEventDisableTiming);
        (void)cudaEventCreateWithFlags(&s_evJoin, cudaEventDisableTiming);
        (void)cudaDeviceSynchronize();
    }
};
static ModulePreload s_preload;
}

// ---------------- host driver -----------------------------------------------
extern "C" void kernel_launch(void* const* d_in, const int* in_sizes, int n_in,
                              void* d_out, int out_size) {
    const float* x  = (const float*)d_in[0];
    const int*   ei = (const int*)d_in[1];
    const int*   ba = (const int*)d_in[2];
    const float* Wl0 = (const float*)d_in[3];
    const float* Wr0 = (const float*)d_in[4];
    const float* at0 = (const float*)d_in[5];
    const float* b0  = (const float*)d_in[6];
    const float* Rw0 = (const float*)d_in[7];
    const float* Rb0 = (const float*)d_in[8];
    const float* Wl1 = (const float*)d_in[9];
    const float* Wr1 = (const float*)d_in[10];
    const float* at1 = (const float*)d_in[11];
    const float* b1  = (const float*)d_in[12];
    const float* Rw1 = (const float*)d_in[13];
    const float* Rb1 = (const float*)d_in[14];
    const float* Wl2 = (const float*)d_in[15];
    const float* Wr2 = (const float*)d_in[16];
    const float* at2 = (const float*)d_in[17];
    const float* b2  = (const float*)d_in[18];
    const float* Rw2 = (const float*)d_in[19];
    const float* Rb2 = (const float*)d_in[20];
    const float* Wf  = (const float*)d_in[21];
    const float* bf  = (const float*)d_in[22];
    float* out = (float*)d_out;

    dim3 ggrid((NN + 127) / 128, 1, 3);
    dim3 ngrid((NN * 16 + 255) / 256);
    size_t gsm = GEMM_SMEM_WORDS * 4;

    // fork: CSR build on s_prep, concurrent with layer-0 GEMM on main stream
    cudaEventRecord(s_evFork, 0);
    cudaStreamWaitEvent(s_prep, s_evFork, 0);
    init_kernel<<<(NN + 255) / 256, 256, 0, s_prep>>>();
    hist_kernel<<<(NE / 4 + 255) / 256, 256, 0, s_prep>>>(ei, ba);
    scan1_kernel<<<SCAN_BLOCKS, 1024, 0, s_prep>>>();
    scan2_kernel<<<1, 64, 0, s_prep>>>();
    scan3_kernel<<<SCAN_BLOCKS, 1024, 0, s_prep>>>();
    scatter_kernel<<<(NE / 4 + NN + 255) / 256, 256, 0, s_prep>>>(ei);
    cudaEventRecord(s_evJoin, s_prep);

    // layer 0 projections overlap with CSR build
    gemm_mma_kernel<<<ggrid, 256, gsm>>>(x, 0, Wl0, Wr0, Rw0, NN, 128);
    cudaStreamWaitEvent(0, s_evJoin, 0);
    gat_node_kernel<<<ngrid, 256>>>(at0, b0, Rb0, 1, 0);

    // layer 1 (K=64), relu
    gemm_mma_kernel<<<ggrid, 256, gsm>>>(nullptr, 1, Wl1, Wr1, Rw1, NN, 64);
    gat_node_kernel<<<ngrid, 256>>>(at1, b1, Rb1, 1, 0);

    // layer 2 (K=64), no relu, fused mean-pool scatter
    gemm_mma_kernel<<<ggrid, 256, gsm>>>(nullptr, 1, Wl2, Wr2, Rw2, NN, 64);
    gat_node_kernel<<<ngrid, 256>>>(at2, b2, Rb2, 0, 1);

    final_kernel<<<1, 256>>>(Wf, bf, out);
}

// round 14
// speedup vs baseline: 1.0952x; 1.0295x over previous
#include <cuda_runtime.h>
#include <cuda_bf16.h>
#include <float.h>
#include <stdint.h>

#define NN 50000
#define NE 1000000
#define ET (NN + NE)
#define HID 64
#define NG 256
#define CSRB 49            // csr blocks (49*1024 >= NN), all co-resident

// ---------------- scratch (static device globals; no runtime allocation) ----
__device__ int   g_cnt[NN];
__device__ int   g_rowptr[NN + 1];
__device__ int   g_cursor[NN];
__device__ int   g_bsum[64];
__device__ int   g_barcnt[4];
__device__ int   g_csrsrc[ET];
__device__ int   g_batch[NN];
__device__ float g_xl[NN * HID];
__device__ float g_xr[NN * HID];
__device__ float g_res[NN * HID];
__device__ float g_xcur[NN * HID];
__device__ float g_sums[NG * HID];
__device__ float g_cntg[NG];

// ---------------- init: zero barrier counters + pool accumulators -----------
__global__ void init_kernel() {
    int i = blockIdx.x * blockDim.x + threadIdx.x;
    if (i < NG * HID) g_sums[i] = 0.f;
    if (i < NG) g_cntg[i] = 0.f;
    if (i < 4) g_barcnt[i] = 0;
}

// ---------------- fused CSR build: init/hist/scan/scatter, 1 kernel ---------
__device__ __forceinline__ void gbar(int k) {
    __syncthreads();
    if (threadIdx.x == 0) {
        __threadfence();
        atomicAdd(&g_barcnt[k], 1);
        while (((volatile int*)g_barcnt)[k] < CSRB) __nanosleep(64);
    }
    __syncthreads();
    __threadfence();
}

__global__ __launch_bounds__(1024) void csr_kernel(const int* __restrict__ ei,
                                                   const int* __restrict__ batch) {
    int b = blockIdx.x, t = threadIdx.x;
    int gt = b * 1024 + t;
    const int GT = CSRB * 1024;

    // phase 0: init counts (=1 for self-loop) + batch convert
    for (int i = gt; i < NN; i += GT) {
        g_cnt[i] = 1;
        g_batch[i] = batch[i];
    }
    gbar(0);

    // phase 1: histogram of dst (int4)
    for (int i = gt; i < NE / 4; i += GT) {
        int4 d4 = ((const int4*)(ei + NE))[i];
        atomicAdd(&g_cnt[d4.x], 1);
        atomicAdd(&g_cnt[d4.y], 1);
        atomicAdd(&g_cnt[d4.z], 1);
        atomicAdd(&g_cnt[d4.w], 1);
    }
    gbar(1);

    // phase 2: scan. idx = gt (49*1024 = 50176 >= NN, one element/thread)
    {
        int idx = gt;
        int lane = t & 31, w = t >> 5;
        int c = (idx < NN) ? g_cnt[idx] : 0;
        int v = c;
#pragma unroll
        for (int o = 1; o < 32; o <<= 1) {
            int u = __shfl_up_sync(0xffffffffu, v, o);
            if (lane >= o) v += u;
        }
        __shared__ int ws[32];
        __shared__ int s_boff;
        if (lane == 31) ws[w] = v;
        __syncthreads();
        if (w == 0) {
            int s = ws[lane];
#pragma unroll
            for (int o = 1; o < 32; o <<= 1) {
                int u = __shfl_up_sync(0xffffffffu, s, o);
                if (lane >= o) s += u;
            }
            ws[lane] = s;
        }
        __syncthreads();
        int incl = v + (w > 0 ? ws[w - 1] : 0);
        if (t == 1023) g_bsum[b] = incl;
        gbar(2);
        if (w == 0) {
            int acc = 0;
            int i0 = lane, i1 = lane + 32;
            if (i0 < b) acc += g_bsum[i0];
            if (i1 < b) acc += g_bsum[i1];
#pragma unroll
            for (int o = 16; o; o >>= 1) acc += __shfl_xor_sync(0xffffffffu, acc, o);
            if (lane == 0) s_boff = acc;
        }
        __syncthreads();
        int boff = s_boff;
        if (idx < NN) {
            int r = incl - c + boff;
            g_rowptr[idx] = r;
            g_cursor[idx] = r;
        }
        if (gt == 0) g_rowptr[NN] = ET;
    }
    gbar(3);

    // phase 3: scatter edges + self-loops
    for (int i = gt; i < NE / 4; i += GT) {
        int4 s4 = ((const int4*)ei)[i];
        int4 d4 = ((const int4*)(ei + NE))[i];
        int p;
        p = atomicAdd(&g_cursor[d4.x], 1); g_csrsrc[p] = s4.x;
        p = atomicAdd(&g_cursor[d4.y], 1); g_csrsrc[p] = s4.y;
        p = atomicAdd(&g_cursor[d4.z], 1); g_csrsrc[p] = s4.z;
        p = atomicAdd(&g_cursor[d4.w], 1); g_csrsrc[p] = s4.w;
    }
    for (int n = gt; n < NN; n += GT) {
        int p = atomicAdd(&g_cursor[n], 1);
        g_csrsrc[p] = n;
    }
}

// ======================= 3xTF32 mma.sync GEMM ================================
#define APAD 36
#define SM_AH 0
#define SM_AL (128 * APAD)
#define SM_WH (SM_AL + 128 * APAD)
#define SM_WL (SM_WH + 64 * APAD)
#define GEMM_SMEM_WORDS (SM_WL + 64 * APAD)   // 13824 words = 55296 B

__device__ __forceinline__ void split_tf32(float x, uint32_t& hi, uint32_t& lo) {
    asm("cvt.rna.tf32.f32 %0, %1;" : "=r"(hi) : "f"(x));
    float l = x - __uint_as_float(hi);
    asm("cvt.rna.tf32.f32 %0, %1;" : "=r"(lo) : "f"(l));
}

#define MMA_TF32(d, a0, a1, a2, a3, b0, b1)                                   \
    asm volatile(                                                             \
        "mma.sync.aligned.m16n8k8.row.col.f32.tf32.tf32.f32 "                 \
        "{%0,%1,%2,%3}, {%4,%5,%6,%7}, {%8,%9}, {%0,%1,%2,%3};"               \
        : "+f"((d)[0]), "+f"((d)[1]), "+f"((d)[2]), "+f"((d)[3])              \
        : "r"(a0), "r"(a1), "r"(a2), "r"(a3), "r"(b0), "r"(b1))

__global__ __launch_bounds__(256) void gemm_mma_kernel(
    const float* __restrict__ Aext, int use_internal,
    const float* __restrict__ Wl, const float* __restrict__ Wr,
    const float* __restrict__ Rw, int M, int K) {
    extern __shared__ uint32_t smu[];

    int z = blockIdx.z;
    const float* __restrict__ W = (z == 0) ? Wl : (z == 1) ? Wr : Rw;
    float* __restrict__ C = (z == 0) ? g_xl : (z == 1) ? g_xr : g_res;
    const float* __restrict__ A = use_internal ? (const float*)g_xcur : Aext;

    int tid = threadIdx.x;
    int warp = tid >> 5;
    int lane = tid & 31;
    int gid = lane >> 2;
    int tig = lane & 3;
    int rowBase = blockIdx.x * 128;

    float acc[8][4];
#pragma unroll
    for (int nt = 0; nt < 8; nt++)
#pragma unroll
        for (int j = 0; j < 4; j++) acc[nt][j] = 0.f;

    for (int k0 = 0; k0 < K; k0 += 32) {
#pragma unroll
        for (int p = 0; p < 4; p++) {
            int lin = tid + p * 256;
            int r = lin >> 3;
            int c = lin & 7;
            int row = rowBase + r;
            float4 f = make_float4(0.f, 0.f, 0.f, 0.f);
            if (row < M) f = *(const float4*)&A[(long)row * K + k0 + c * 4];
            uint4 h, l;
            split_tf32(f.x, h.x, l.x);
            split_tf32(f.y, h.y, l.y);
            split_tf32(f.z, h.z, l.z);
            split_tf32(f.w, h.w, l.w);
            *(uint4*)&smu[SM_AH + r * APAD + c * 4] = h;
            *(uint4*)&smu[SM_AL + r * APAD + c * 4] = l;
        }
#pragma unroll
        for (int p = 0; p < 2; p++) {
            int lin = tid + p * 256;
            int n = lin >> 3;
            int c = lin & 7;
            float4 f = *(const float4*)&W[n * K + k0 + c * 4];
            uint4 h, l;
            split_tf32(f.x, h.x, l.x);
            split_tf32(f.y, h.y, l.y);
            split_tf32(f.z, h.z, l.z);
            split_tf32(f.w, h.w, l.w);
            *(uint4*)&smu[SM_WH + n * APAD + c * 4] = h;
            *(uint4*)&smu[SM_WL + n * APAD + c * 4] = l;
        }
        __syncthreads();

#pragma unroll
        for (int kk = 0; kk < 4; kk++) {
            int kb = kk * 8;
            int r0 = warp * 16 + gid;
            uint32_t ah0 = smu[SM_AH + r0 * APAD + kb + tig];
            uint32_t ah1 = smu[SM_AH + (r0 + 8) * APAD + kb + tig];
            uint32_t ah2 = smu[SM_AH + r0 * APAD + kb + tig + 4];
            uint32_t ah3 = smu[SM_AH + (r0 + 8) * APAD + kb + tig + 4];
            uint32_t al0 = smu[SM_AL + r0 * APAD + kb + tig];
            uint32_t al1 = smu[SM_AL + (r0 + 8) * APAD + kb + tig];
            uint32_t al2 = smu[SM_AL + r0 * APAD + kb + tig + 4];
            uint32_t al3 = smu[SM_AL + (r0 + 8) * APAD + kb + tig + 4];
#pragma unroll
            for (int nt = 0; nt < 8; nt++) {
                int bn = nt * 8 + gid;
                uint32_t bh0 = smu[SM_WH + bn * APAD + kb + tig];
                uint32_t bh1 = smu[SM_WH + bn * APAD + kb + tig + 4];
                uint32_t bl0 = smu[SM_WL + bn * APAD + kb + tig];
                uint32_t bl1 = smu[SM_WL + bn * APAD + kb + tig + 4];
                MMA_TF32(acc[nt], ah0, ah1, ah2, ah3, bh0, bh1);
                MMA_TF32(acc[nt], ah0, ah1, ah2, ah3, bl0, bl1);
                MMA_TF32(acc[nt], al0, al1, al2, al3, bh0, bh1);
            }
        }
        __syncthreads();
    }

    int r0 = rowBase + warp * 16 + gid;
    int r1 = r0 + 8;
#pragma unroll
    for (int nt = 0; nt < 8; nt++) {
        int n0 = nt * 8 + 2 * tig;
        if (r0 < M) *(float2*)&C[(long)r0 * HID + n0] = make_float2(acc[nt][0], acc[nt][1]);
        if (r1 < M) *(float2*)&C[(long)r1 * HID + n0] = make_float2(acc[nt][2], acc[nt][3]);
    }
}

// ---------------- GATv2 aggregation: half-warp per node, plain softmax ------
__global__ __launch_bounds__(256) void gat_node_kernel(
    const float* __restrict__ att, const float* __restrict__ bia,
    const float* __restrict__ Rb, int relu_flag, int fuse_pool) {
    int gtid = blockIdx.x * blockDim.x + threadIdx.x;
    int n = gtid >> 4;
    if (n >= NN) return;
    int l = threadIdx.x & 15;
    unsigned mask = 0xFFFFu << (threadIdx.x & 16);
    int c0 = l * 4;

    const float4 xrn = *(const float4*)&g_xr[n * HID + c0];
    const float4 av  = *(const float4*)&att[c0];

    float den = 0.f;
    float4 acc = make_float4(0.f, 0.f, 0.f, 0.f);

    int e = g_rowptr[n], end = g_rowptr[n + 1];
    for (; e < end; e++) {
        int s = g_csrsrc[e];
        float4 x = *(const float4*)&g_xl[s * HID + c0];
        float v0 = x.x + xrn.x; v0 = fmaxf(v0, 0.2f * v0);
        float v1 = x.y + xrn.y; v1 = fmaxf(v1, 0.2f * v1);
        float v2 = x.z + xrn.z; v2 = fmaxf(v2, 0.2f * v2);
        float v3 = x.w + xrn.w; v3 = fmaxf(v3, 0.2f * v3);
        float p = fmaf(v0, av.x, fmaf(v1, av.y, fmaf(v2, av.z, v3 * av.w)));
        p += __shfl_xor_sync(mask, p, 1);
        p += __shfl_xor_sync(mask, p, 2);
        p += __shfl_xor_sync(mask, p, 4);
        p += __shfl_xor_sync(mask, p, 8);
        float w = __expf(p);
        den += w;
        acc.x = fmaf(w, x.x, acc.x);
        acc.y = fmaf(w, x.y, acc.y);
        acc.z = fmaf(w, x.z, acc.z);
        acc.w = fmaf(w, x.w, acc.w);
    }
    float inv = 1.f / den;   // self-loop guarantees den > 0
    float4 r4 = *(const float4*)&g_res[n * HID + c0];
    float4 b4 = *(const float4*)&bia[c0];
    float4 rb4 = *(const float4*)&Rb[c0];
    float h0 = acc.x * inv + b4.x + r4.x + rb4.x;
    float h1 = acc.y * inv + b4.y + r4.y + rb4.y;
    float h2 = acc.z * inv + b4.z + r4.z + rb4.z;
    float h3 = acc.w * inv + b4.w + r4.w + rb4.w;
    if (relu_flag) {
        h0 = fmaxf(h0, 0.f); h1 = fmaxf(h1, 0.f);
        h2 = fmaxf(h2, 0.f); h3 = fmaxf(h3, 0.f);
    }
    if (!fuse_pool) {
        *(float4*)&g_xcur[n * HID + c0] = make_float4(h0, h1, h2, h3);
    } else {
        int g = g_batch[n];
        atomicAdd(&g_sums[g * HID + c0 + 0], h0);
        atomicAdd(&g_sums[g * HID + c0 + 1], h1);
        atomicAdd(&g_sums[g * HID + c0 + 2], h2);
        atomicAdd(&g_sums[g * HID + c0 + 3], h3);
        if (l == 0) atomicAdd(&g_cntg[g], 1.f);
    }
}

// ---------------- final: mean pool division + linear head -------------------
__global__ void final_kernel(const float* __restrict__ Wf,
                             const float* __restrict__ bf,
                             float* __restrict__ out) {
    int g = blockIdx.x * blockDim.x + threadIdx.x;
    if (g >= NG) return;
    float acc = 0.f;
#pragma unroll
    for (int c = 0; c < HID; c++) acc += g_sums[g * HID + c] * Wf[c];
    float cnt = fmaxf(g_cntg[g], 1.f);
    out[g] = acc / cnt + bf[0];
}

// --------- static stream/event for prep/GEMM overlap (created pre-baseline) -
namespace {
cudaStream_t s_prep = nullptr;
cudaEvent_t  s_evFork = nullptr, s_evJoin = nullptr;
struct ModulePreload {
    ModulePreload() {
        float z = 0.f;
        (void)cudaMemcpyToSymbol(g_cntg, &z, sizeof(float));
        (void)cudaFuncSetAttribute(gemm_mma_kernel,
                                   cudaFuncAttributeMaxDynamicSharedMemorySize,
                                   GEMM_SMEM_WORDS * 4);
        (void)cudaStreamCreateWithFlags(&s_prep, cudaStreamNonBlocking);
        (void)cudaEventCreateWithFlags(&s_evFork, cudaEventDisableTiming);
        (void)cudaEventCreateWithFlags(&s_evJoin, cudaEventDisableTiming);
        (void)cudaDeviceSynchronize();
    }
};
static ModulePreload s_preload;
}

// ---------------- host driver -----------------------------------------------
extern "C" void kernel_launch(void* const* d_in, const int* in_sizes, int n_in,
                              void* d_out, int out_size) {
    const float* x  = (const float*)d_in[0];
    const int*   ei = (const int*)d_in[1];
    const int*   ba = (const int*)d_in[2];
    const float* Wl0 = (const float*)d_in[3];
    const float* Wr0 = (const float*)d_in[4];
    const float* at0 = (const float*)d_in[5];
    const float* b0  = (const float*)d_in[6];
    const float* Rw0 = (const float*)d_in[7];
    const float* Rb0 = (const float*)d_in[8];
    const float* Wl1 = (const float*)d_in[9];
    const float* Wr1 = (const float*)d_in[10];
    const float* at1 = (const float*)d_in[11];
    const float* b1  = (const float*)d_in[12];
    const float* Rw1 = (const float*)d_in[13];
    const float* Rb1 = (const float*)d_in[14];
    const float* Wl2 = (const float*)d_in[15];
    const float* Wr2 = (const float*)d_in[16];
    const float* at2 = (const float*)d_in[17];
    const float* b2  = (const float*)d_in[18];
    const float* Rw2 = (const float*)d_in[19];
    const float* Rb2 = (const float*)d_in[20];
    const float* Wf  = (const float*)d_in[21];
    const float* bf  = (const float*)d_in[22];
    float* out = (float*)d_out;

    dim3 ggrid((NN + 127) / 128, 1, 3);
    dim3 ngrid((NN * 16 + 255) / 256);
    size_t gsm = GEMM_SMEM_WORDS * 4;

    // fork: CSR build (2 launches) on s_prep, overlapping layer-0 GEMM.
    // Submission order puts gat0 at global launch index 3 (ncu -s window).
    cudaEventRecord(s_evFork, 0);
    cudaStreamWaitEvent(s_prep, s_evFork, 0);
    init_kernel<<<(NG * HID + 255) / 256, 256, 0, s_prep>>>();        // #0
    csr_kernel<<<CSRB, 1024, 0, s_prep>>>(ei, ba);                    // #1
    cudaEventRecord(s_evJoin, s_prep);

    gemm_mma_kernel<<<ggrid, 256, gsm>>>(x, 0, Wl0, Wr0, Rw0, NN, 128);  // #2
    cudaStreamWaitEvent(0, s_evJoin, 0);
    gat_node_kernel<<<ngrid, 256>>>(at0, b0, Rb0, 1, 0);              // #3 <- profiled

    gemm_mma_kernel<<<ggrid, 256, gsm>>>(nullptr, 1, Wl1, Wr1, Rw1, NN, 64);
    gat_node_kernel<<<ngrid, 256>>>(at1, b1, Rb1, 1, 0);

    gemm_mma_kernel<<<ggrid, 256, gsm>>>(nullptr, 1, Wl2, Wr2, Rw2, NN, 64);
    gat_node_kernel<<<ngrid, 256>>>(at2, b2, Rb2, 0, 1);

    final_kernel<<<1, 256>>>(Wf, bf, out);
}

// round 15
// speedup vs baseline: 1.1419x; 1.0426x over previous
#include <cuda_runtime.h>
#include <cuda_bf16.h>
#include <float.h>
#include <stdint.h>

#define NN 50000
#define NE 1000000
#define ET (NN + NE)
#define HID 64
#define NG 256
#define CSRB 49            // csr blocks (49*1024 >= NN), all co-resident

// ---------------- scratch (static device globals; no runtime allocation) ----
__device__ int   g_cnt[NN];
__device__ int   g_rowptr[NN + 1];
__device__ int   g_cursor[NN];
__device__ int   g_bsum[64];
__device__ int   g_barcnt[4];
__device__ int   g_csrsrc[ET];
__device__ int   g_batch[NN];
__device__ float g_xl[NN * HID];
__device__ float g_xr[NN * HID];
__device__ float g_res[NN * HID];
__device__ float g_xcur[NN * HID];
__device__ float g_sums[NG * HID];
__device__ float g_cntg[NG];

// ---------------- init: zero barrier counters + pool accumulators -----------
__global__ void init_kernel() {
    int i = blockIdx.x * blockDim.x + threadIdx.x;
    if (i < NG * HID) g_sums[i] = 0.f;
    if (i < NG) g_cntg[i] = 0.f;
    if (i < 4) g_barcnt[i] = 0;
}

// ---------------- fused CSR build: init/hist/scan/scatter, 1 kernel ---------
__device__ __forceinline__ void gbar(int k) {
    __syncthreads();
    if (threadIdx.x == 0) {
        __threadfence();
        atomicAdd(&g_barcnt[k], 1);
        while (((volatile int*)g_barcnt)[k] < CSRB) __nanosleep(64);
    }
    __syncthreads();
    __threadfence();
}

__global__ __launch_bounds__(1024) void csr_kernel(const int* __restrict__ ei,
                                                   const int* __restrict__ batch) {
    int b = blockIdx.x, t = threadIdx.x;
    int gt = b * 1024 + t;
    const int GT = CSRB * 1024;

    for (int i = gt; i < NN; i += GT) {
        g_cnt[i] = 1;
        g_batch[i] = batch[i];
    }
    gbar(0);

    for (int i = gt; i < NE / 4; i += GT) {
        int4 d4 = ((const int4*)(ei + NE))[i];
        atomicAdd(&g_cnt[d4.x], 1);
        atomicAdd(&g_cnt[d4.y], 1);
        atomicAdd(&g_cnt[d4.z], 1);
        atomicAdd(&g_cnt[d4.w], 1);
    }
    gbar(1);

    {
        int idx = gt;
        int lane = t & 31, w = t >> 5;
        int c = (idx < NN) ? g_cnt[idx] : 0;
        int v = c;
#pragma unroll
        for (int o = 1; o < 32; o <<= 1) {
            int u = __shfl_up_sync(0xffffffffu, v, o);
            if (lane >= o) v += u;
        }
        __shared__ int ws[32];
        __shared__ int s_boff;
        if (lane == 31) ws[w] = v;
        __syncthreads();
        if (w == 0) {
            int s = ws[lane];
#pragma unroll
            for (int o = 1; o < 32; o <<= 1) {
                int u = __shfl_up_sync(0xffffffffu, s, o);
                if (lane >= o) s += u;
            }
            ws[lane] = s;
        }
        __syncthreads();
        int incl = v + (w > 0 ? ws[w - 1] : 0);
        if (t == 1023) g_bsum[b] = incl;
        gbar(2);
        if (w == 0) {
            int acc = 0;
            int i0 = lane, i1 = lane + 32;
            if (i0 < b) acc += g_bsum[i0];
            if (i1 < b) acc += g_bsum[i1];
#pragma unroll
            for (int o = 16; o; o >>= 1) acc += __shfl_xor_sync(0xffffffffu, acc, o);
            if (lane == 0) s_boff = acc;
        }
        __syncthreads();
        int boff = s_boff;
        if (idx < NN) {
            int r = incl - c + boff;
            g_rowptr[idx] = r;
            g_cursor[idx] = r;
        }
        if (gt == 0) g_rowptr[NN] = ET;
    }
    gbar(3);

    for (int i = gt; i < NE / 4; i += GT) {
        int4 s4 = ((const int4*)ei)[i];
        int4 d4 = ((const int4*)(ei + NE))[i];
        int p;
        p = atomicAdd(&g_cursor[d4.x], 1); g_csrsrc[p] = s4.x;
        p = atomicAdd(&g_cursor[d4.y], 1); g_csrsrc[p] = s4.y;
        p = atomicAdd(&g_cursor[d4.z], 1); g_csrsrc[p] = s4.z;
        p = atomicAdd(&g_cursor[d4.w], 1); g_csrsrc[p] = s4.w;
    }
    for (int n = gt; n < NN; n += GT) {
        int p = atomicAdd(&g_cursor[n], 1);
        g_csrsrc[p] = n;
    }
}

// ======================= 3xTF32 mma.sync GEMM ================================
#define APAD 36
#define SM_AH 0
#define SM_AL (128 * APAD)
#define SM_WH (SM_AL + 128 * APAD)
#define SM_WL (SM_WH + 64 * APAD)
#define GEMM_SMEM_WORDS (SM_WL + 64 * APAD)   // 13824 words = 55296 B

__device__ __forceinline__ void split_tf32(float x, uint32_t& hi, uint32_t& lo) {
    asm("cvt.rna.tf32.f32 %0, %1;" : "=r"(hi) : "f"(x));
    float l = x - __uint_as_float(hi);
    asm("cvt.rna.tf32.f32 %0, %1;" : "=r"(lo) : "f"(l));
}

#define MMA_TF32(d, a0, a1, a2, a3, b0, b1)                                   \
    asm volatile(                                                             \
        "mma.sync.aligned.m16n8k8.row.col.f32.tf32.tf32.f32 "                 \
        "{%0,%1,%2,%3}, {%4,%5,%6,%7}, {%8,%9}, {%0,%1,%2,%3};"               \
        : "+f"((d)[0]), "+f"((d)[1]), "+f"((d)[2]), "+f"((d)[3])              \
        : "r"(a0), "r"(a1), "r"(a2), "r"(a3), "r"(b0), "r"(b1))

__global__ __launch_bounds__(256) void gemm_mma_kernel(
    const float* __restrict__ Aext, int use_internal,
    const float* __restrict__ Wl, const float* __restrict__ Wr,
    const float* __restrict__ Rw, int M, int K) {
    extern __shared__ uint32_t smu[];

    int z = blockIdx.z;
    const float* __restrict__ W = (z == 0) ? Wl : (z == 1) ? Wr : Rw;
    float* __restrict__ C = (z == 0) ? g_xl : (z == 1) ? g_xr : g_res;
    const float* __restrict__ A = use_internal ? (const float*)g_xcur : Aext;

    int tid = threadIdx.x;
    int warp = tid >> 5;
    int lane = tid & 31;
    int gid = lane >> 2;
    int tig = lane & 3;
    int rowBase = blockIdx.x * 128;

    float acc[8][4];
#pragma unroll
    for (int nt = 0; nt < 8; nt++)
#pragma unroll
        for (int j = 0; j < 4; j++) acc[nt][j] = 0.f;

    for (int k0 = 0; k0 < K; k0 += 32) {
#pragma unroll
        for (int p = 0; p < 4; p++) {
            int lin = tid + p * 256;
            int r = lin >> 3;
            int c = lin & 7;
            int row = rowBase + r;
            float4 f = make_float4(0.f, 0.f, 0.f, 0.f);
            if (row < M) f = *(const float4*)&A[(long)row * K + k0 + c * 4];
            uint4 h, l;
            split_tf32(f.x, h.x, l.x);
            split_tf32(f.y, h.y, l.y);
            split_tf32(f.z, h.z, l.z);
            split_tf32(f.w, h.w, l.w);
            *(uint4*)&smu[SM_AH + r * APAD + c * 4] = h;
            *(uint4*)&smu[SM_AL + r * APAD + c * 4] = l;
        }
#pragma unroll
        for (int p = 0; p < 2; p++) {
            int lin = tid + p * 256;
            int n = lin >> 3;
            int c = lin & 7;
            float4 f = *(const float4*)&W[n * K + k0 + c * 4];
            uint4 h, l;
            split_tf32(f.x, h.x, l.x);
            split_tf32(f.y, h.y, l.y);
            split_tf32(f.z, h.z, l.z);
            split_tf32(f.w, h.w, l.w);
            *(uint4*)&smu[SM_WH + n * APAD + c * 4] = h;
            *(uint4*)&smu[SM_WL + n * APAD + c * 4] = l;
        }
        __syncthreads();

#pragma unroll
        for (int kk = 0; kk < 4; kk++) {
            int kb = kk * 8;
            int r0 = warp * 16 + gid;
            uint32_t ah0 = smu[SM_AH + r0 * APAD + kb + tig];
            uint32_t ah1 = smu[SM_AH + (r0 + 8) * APAD + kb + tig];
            uint32_t ah2 = smu[SM_AH + r0 * APAD + kb + tig + 4];
            uint32_t ah3 = smu[SM_AH + (r0 + 8) * APAD + kb + tig + 4];
            uint32_t al0 = smu[SM_AL + r0 * APAD + kb + tig];
            uint32_t al1 = smu[SM_AL + (r0 + 8) * APAD + kb + tig];
            uint32_t al2 = smu[SM_AL + r0 * APAD + kb + tig + 4];
            uint32_t al3 = smu[SM_AL + (r0 + 8) * APAD + kb + tig + 4];
#pragma unroll
            for (int nt = 0; nt < 8; nt++) {
                int bn = nt * 8 + gid;
                uint32_t bh0 = smu[SM_WH + bn * APAD + kb + tig];
                uint32_t bh1 = smu[SM_WH + bn * APAD + kb + tig + 4];
                uint32_t bl0 = smu[SM_WL + bn * APAD + kb + tig];
                uint32_t bl1 = smu[SM_WL + bn * APAD + kb + tig + 4];
                MMA_TF32(acc[nt], ah0, ah1, ah2, ah3, bh0, bh1);
                MMA_TF32(acc[nt], ah0, ah1, ah2, ah3, bl0, bl1);
                MMA_TF32(acc[nt], al0, al1, al2, al3, bh0, bh1);
            }
        }
        __syncthreads();
    }

    int r0 = rowBase + warp * 16 + gid;
    int r1 = r0 + 8;
#pragma unroll
    for (int nt = 0; nt < 8; nt++) {
        int n0 = nt * 8 + 2 * tig;
        if (r0 < M) *(float2*)&C[(long)r0 * HID + n0] = make_float2(acc[nt][0], acc[nt][1]);
        if (r1 < M) *(float2*)&C[(long)r1 * HID + n0] = make_float2(acc[nt][2], acc[nt][3]);
    }
}

// ---------------- GATv2 aggregation: half-warp per node, plain softmax ------
// Issue-bound (ncu: issue 57%, fma 30% + alu 18%), so minimize ops/edge:
//   att·leaky(u) = (0.6·att)·u + (0.4·att)·|u|   (exact for slope 0.2)
// and 2-edge unroll to halve loop overhead + double ILP.
__global__ __launch_bounds__(256) void gat_node_kernel(
    const float* __restrict__ att, const float* __restrict__ bia,
    const float* __restrict__ Rb, int relu_flag, int fuse_pool) {
    int gtid = blockIdx.x * blockDim.x + threadIdx.x;
    int n = gtid >> 4;
    if (n >= NN) return;
    int l = threadIdx.x & 15;
    unsigned mask = 0xFFFFu << (threadIdx.x & 16);
    int c0 = l * 4;

    const float4 xrn = *(const float4*)&g_xr[n * HID + c0];
    float4 a6 = *(const float4*)&att[c0];
    float4 a4 = make_float4(0.4f * a6.x, 0.4f * a6.y, 0.4f * a6.z, 0.4f * a6.w);
    a6.x *= 0.6f; a6.y *= 0.6f; a6.z *= 0.6f; a6.w *= 0.6f;

    float den = 0.f;
    float4 acc = make_float4(0.f, 0.f, 0.f, 0.f);

    int e = g_rowptr[n], end = g_rowptr[n + 1];
    for (; e + 1 < end; e += 2) {
        int s0 = g_csrsrc[e];
        int s1 = g_csrsrc[e + 1];
        float4 x0 = *(const float4*)&g_xl[s0 * HID + c0];
        float4 x1 = *(const float4*)&g_xl[s1 * HID + c0];

        float u00 = x0.x + xrn.x, u01 = x0.y + xrn.y;
        float u02 = x0.z + xrn.z, u03 = x0.w + xrn.w;
        float u10 = x1.x + xrn.x, u11 = x1.y + xrn.y;
        float u12 = x1.z + xrn.z, u13 = x1.w + xrn.w;

        float p0 = fmaf(a6.x, u00, fmaf(a6.y, u01, fmaf(a6.z, u02, a6.w * u03)));
        p0 = fmaf(a4.x, fabsf(u00), fmaf(a4.y, fabsf(u01),
             fmaf(a4.z, fabsf(u02), fmaf(a4.w, fabsf(u03), p0))));
        float p1 = fmaf(a6.x, u10, fmaf(a6.y, u11, fmaf(a6.z, u12, a6.w * u13)));
        p1 = fmaf(a4.x, fabsf(u10), fmaf(a4.y, fabsf(u11),
             fmaf(a4.z, fabsf(u12), fmaf(a4.w, fabsf(u13), p1))));

        p0 += __shfl_xor_sync(mask, p0, 1);
        p1 += __shfl_xor_sync(mask, p1, 1);
        p0 += __shfl_xor_sync(mask, p0, 2);
        p1 += __shfl_xor_sync(mask, p1, 2);
        p0 += __shfl_xor_sync(mask, p0, 4);
        p1 += __shfl_xor_sync(mask, p1, 4);
        p0 += __shfl_xor_sync(mask, p0, 8);
        p1 += __shfl_xor_sync(mask, p1, 8);

        float w0 = __expf(p0);
        float w1 = __expf(p1);
        den += w0;
        den += w1;
        acc.x = fmaf(w0, x0.x, acc.x); acc.y = fmaf(w0, x0.y, acc.y);
        acc.z = fmaf(w0, x0.z, acc.z); acc.w = fmaf(w0, x0.w, acc.w);
        acc.x = fmaf(w1, x1.x, acc.x); acc.y = fmaf(w1, x1.y, acc.y);
        acc.z = fmaf(w1, x1.z, acc.z); acc.w = fmaf(w1, x1.w, acc.w);
    }
    if (e < end) {
        int s0 = g_csrsrc[e];
        float4 x0 = *(const float4*)&g_xl[s0 * HID + c0];
        float u00 = x0.x + xrn.x, u01 = x0.y + xrn.y;
        float u02 = x0.z + xrn.z, u03 = x0.w + xrn.w;
        float p0 = fmaf(a6.x, u00, fmaf(a6.y, u01, fmaf(a6.z, u02, a6.w * u03)));
        p0 = fmaf(a4.x, fabsf(u00), fmaf(a4.y, fabsf(u01),
             fmaf(a4.z, fabsf(u02), fmaf(a4.w, fabsf(u03), p0))));
        p0 += __shfl_xor_sync(mask, p0, 1);
        p0 += __shfl_xor_sync(mask, p0, 2);
        p0 += __shfl_xor_sync(mask, p0, 4);
        p0 += __shfl_xor_sync(mask, p0, 8);
        float w0 = __expf(p0);
        den += w0;
        acc.x = fmaf(w0, x0.x, acc.x); acc.y = fmaf(w0, x0.y, acc.y);
        acc.z = fmaf(w0, x0.z, acc.z); acc.w = fmaf(w0, x0.w, acc.w);
    }

    float inv = 1.f / den;   // self-loop guarantees den > 0
    float4 r4 = *(const float4*)&g_res[n * HID + c0];
    float4 b4 = *(const float4*)&bia[c0];
    float4 rb4 = *(const float4*)&Rb[c0];
    float h0 = acc.x * inv + b4.x + r4.x + rb4.x;
    float h1 = acc.y * inv + b4.y + r4.y + rb4.y;
    float h2 = acc.z * inv + b4.z + r4.z + rb4.z;
    float h3 = acc.w * inv + b4.w + r4.w + rb4.w;
    if (relu_flag) {
        h0 = fmaxf(h0, 0.f); h1 = fmaxf(h1, 0.f);
        h2 = fmaxf(h2, 0.f); h3 = fmaxf(h3, 0.f);
    }
    if (!fuse_pool) {
        *(float4*)&g_xcur[n * HID + c0] = make_float4(h0, h1, h2, h3);
    } else {
        int g = g_batch[n];
        atomicAdd(&g_sums[g * HID + c0 + 0], h0);
        atomicAdd(&g_sums[g * HID + c0 + 1], h1);
        atomicAdd(&g_sums[g * HID + c0 + 2], h2);
        atomicAdd(&g_sums[g * HID + c0 + 3], h3);
        if (l == 0) atomicAdd(&g_cntg[g], 1.f);
    }
}

// ---------------- final: mean pool division + linear head -------------------
__global__ void final_kernel(const float* __restrict__ Wf,
                             const float* __restrict__ bf,
                             float* __restrict__ out) {
    int g = blockIdx.x * blockDim.x + threadIdx.x;
    if (g >= NG) return;
    float acc = 0.f;
#pragma unroll
    for (int c = 0; c < HID; c++) acc += g_sums[g * HID + c] * Wf[c];
    float cnt = fmaxf(g_cntg[g], 1.f);
    out[g] = acc / cnt + bf[0];
}

// --------- static stream/event for prep/GEMM overlap (created pre-baseline) -
namespace {
cudaStream_t s_prep = nullptr;
cudaEvent_t  s_evFork = nullptr, s_evJoin = nullptr;
struct ModulePreload {
    ModulePreload() {
        float z = 0.f;
        (void)cudaMemcpyToSymbol(g_cntg, &z, sizeof(float));
        (void)cudaFuncSetAttribute(gemm_mma_kernel,
                                   cudaFuncAttributeMaxDynamicSharedMemorySize,
                                   GEMM_SMEM_WORDS * 4);
        (void)cudaStreamCreateWithFlags(&s_prep, cudaStreamNonBlocking);
        (void)cudaEventCreateWithFlags(&s_evFork, cudaEventDisableTiming);
        (void)cudaEventCreateWithFlags(&s_evJoin, cudaEventDisableTiming);
        (void)cudaDeviceSynchronize();
    }
};
static ModulePreload s_preload;
}

// ---------------- host driver -----------------------------------------------
extern "C" void kernel_launch(void* const* d_in, const int* in_sizes, int n_in,
                              void* d_out, int out_size) {
    const float* x  = (const float*)d_in[0];
    const int*   ei = (const int*)d_in[1];
    const int*   ba = (const int*)d_in[2];
    const float* Wl0 = (const float*)d_in[3];
    const float* Wr0 = (const float*)d_in[4];
    const float* at0 = (const float*)d_in[5];
    const float* b0  = (const float*)d_in[6];
    const float* Rw0 = (const float*)d_in[7];
    const float* Rb0 = (const float*)d_in[8];
    const float* Wl1 = (const float*)d_in[9];
    const float* Wr1 = (const float*)d_in[10];
    const float* at1 = (const float*)d_in[11];
    const float* b1  = (const float*)d_in[12];
    const float* Rw1 = (const float*)d_in[13];
    const float* Rb1 = (const float*)d_in[14];
    const float* Wl2 = (const float*)d_in[15];
    const float* Wr2 = (const float*)d_in[16];
    const float* at2 = (const float*)d_in[17];
    const float* b2  = (const float*)d_in[18];
    const float* Rw2 = (const float*)d_in[19];
    const float* Rb2 = (const float*)d_in[20];
    const float* Wf  = (const float*)d_in[21];
    const float* bf  = (const float*)d_in[22];
    float* out = (float*)d_out;

    dim3 ggrid((NN + 127) / 128, 1, 3);
    dim3 ngrid((NN * 16 + 255) / 256);
    size_t gsm = GEMM_SMEM_WORDS * 4;

    // fork: CSR build (2 launches) on s_prep, overlapping layer-0 GEMM.
    cudaEventRecord(s_evFork, 0);
    cudaStreamWaitEvent(s_prep, s_evFork, 0);
    init_kernel<<<(NG * HID + 255) / 256, 256, 0, s_prep>>>();        // #0
    csr_kernel<<<CSRB, 1024, 0, s_prep>>>(ei, ba);                    // #1
    cudaEventRecord(s_evJoin, s_prep);

    gemm_mma_kernel<<<ggrid, 256, gsm>>>(x, 0, Wl0, Wr0, Rw0, NN, 128);  // #2
    cudaStreamWaitEvent(0, s_evJoin, 0);
    gat_node_kernel<<<ngrid, 256>>>(at0, b0, Rb0, 1, 0);              // #3

    gemm_mma_kernel<<<ggrid, 256, gsm>>>(nullptr, 1, Wl1, Wr1, Rw1, NN, 64);  // #4
    gat_node_kernel<<<ngrid, 256>>>(at1, b1, Rb1, 1, 0);              // #5 <- profiled

    gemm_mma_kernel<<<ggrid, 256, gsm>>>(nullptr, 1, Wl2, Wr2, Rw2, NN, 64);
    gat_node_kernel<<<ngrid, 256>>>(at2, b2, Rb2, 0, 1);

    final_kernel<<<1, 256>>>(Wf, bf, out);
}

// round 16
// speedup vs baseline: 1.1947x; 1.0462x over previous
#include <cuda_runtime.h>
#include <cuda_bf16.h>
#include <float.h>
#include <stdint.h>

#define NN 50000
#define NE 1000000
#define ET (NN + NE)
#define HID 64
#define NG 256
#define CSRB 49            // csr blocks (49*1024 >= NN), all co-resident

// ---------------- scratch (static device globals; no runtime allocation) ----
__device__ int   g_cnt[NN];
__device__ int   g_rowptr[NN + 1];
__device__ int   g_cursor[NN];
__device__ int   g_bsum[64];
__device__ int   g_barcnt[8];
__device__ int   g_dhist[256];
__device__ int   g_doff[256];
__device__ int   g_perm[NN];
__device__ int   g_csrsrc[ET];
__device__ int   g_batch[NN];
__device__ float g_xl[NN * HID];
__device__ float g_xr[NN * HID];
__device__ float g_res[NN * HID];
__device__ float g_xcur[NN * HID];
__device__ float g_sums[NG * HID];
__device__ float g_cntg[NG];

// ---------------- init: zero barrier counters + pool accumulators -----------
__global__ void init_kernel() {
    int i = blockIdx.x * blockDim.x + threadIdx.x;
    if (i < NG * HID) g_sums[i] = 0.f;
    if (i < NG) g_cntg[i] = 0.f;
    if (i < 8) g_barcnt[i] = 0;
    if (i < 256) g_dhist[i] = 0;
}

// ---------------- fused CSR build + degree sort, 1 kernel --------------------
__device__ __forceinline__ void gbar(int k) {
    __syncthreads();
    if (threadIdx.x == 0) {
        __threadfence();
        atomicAdd(&g_barcnt[k], 1);
        while (((volatile int*)g_barcnt)[k] < CSRB) __nanosleep(64);
    }
    __syncthreads();
    __threadfence();
}

__global__ __launch_bounds__(1024) void csr_kernel(const int* __restrict__ ei,
                                                   const int* __restrict__ batch) {
    int b = blockIdx.x, t = threadIdx.x;
    int gt = b * 1024 + t;
    const int GT = CSRB * 1024;

    // phase 0: init counts (=1 for self-loop) + batch convert
    for (int i = gt; i < NN; i += GT) {
        g_cnt[i] = 1;
        g_batch[i] = batch[i];
    }
    gbar(0);

    // phase 1: histogram of dst (int4)
    for (int i = gt; i < NE / 4; i += GT) {
        int4 d4 = ((const int4*)(ei + NE))[i];
        atomicAdd(&g_cnt[d4.x], 1);
        atomicAdd(&g_cnt[d4.y], 1);
        atomicAdd(&g_cnt[d4.z], 1);
        atomicAdd(&g_cnt[d4.w], 1);
    }
    gbar(1);

    // phase 2: scan for rowptr + degree histogram
    {
        int idx = gt;
        int lane = t & 31, w = t >> 5;
        int c = (idx < NN) ? g_cnt[idx] : 0;
        int v = c;
#pragma unroll
        for (int o = 1; o < 32; o <<= 1) {
            int u = __shfl_up_sync(0xffffffffu, v, o);
            if (lane >= o) v += u;
        }
        __shared__ int ws[32];
        __shared__ int s_boff;
        if (lane == 31) ws[w] = v;
        __syncthreads();
        if (w == 0) {
            int s = ws[lane];
#pragma unroll
            for (int o = 1; o < 32; o <<= 1) {
                int u = __shfl_up_sync(0xffffffffu, s, o);
                if (lane >= o) s += u;
            }
            ws[lane] = s;
        }
        __syncthreads();
        int incl = v + (w > 0 ? ws[w - 1] : 0);
        if (t == 1023) g_bsum[b] = incl;
        gbar(2);
        if (w == 0) {
            int acc = 0;
            int i0 = lane, i1 = lane + 32;
            if (i0 < b) acc += g_bsum[i0];
            if (i1 < b) acc += g_bsum[i1];
#pragma unroll
            for (int o = 16; o; o >>= 1) acc += __shfl_xor_sync(0xffffffffu, acc, o);
            if (lane == 0) s_boff = acc;
        }
        __syncthreads();
        int boff = s_boff;
        if (idx < NN) {
            int r = incl - c + boff;
            g_rowptr[idx] = r;
            g_cursor[idx] = r;
            atomicAdd(&g_dhist[c < 255 ? c : 255], 1);  // degree histogram
        }
        if (gt == 0) g_rowptr[NN] = ET;
    }
    gbar(3);

    // phase 2b: exclusive scan of the 256 degree bins (block 0, warp 0)
    if (b == 0 && t < 32) {
        int base = t * 8;
        int v[8];
        int tot = 0;
#pragma unroll
        for (int j = 0; j < 8; j++) { v[j] = tot; tot += g_dhist[base + j]; }
        int incl = tot;
#pragma unroll
        for (int o = 1; o < 32; o <<= 1) {
            int u = __shfl_up_sync(0xffffffffu, incl, o);
            if (t >= o) incl += u;
        }
        int lane_excl = incl - tot;
#pragma unroll
        for (int j = 0; j < 8; j++) g_doff[base + j] = lane_excl + v[j];
    }
    gbar(4);

    // phase 2c: scatter node ids into degree-sorted permutation
    for (int i = gt; i < NN; i += GT) {
        int d = g_cnt[i]; d = d < 255 ? d : 255;
        int pos = atomicAdd(&g_doff[d], 1);
        g_perm[pos] = i;
    }

    // phase 3: scatter edges + self-loops (needs bar3 only)
    for (int i = gt; i < NE / 4; i += GT) {
        int4 s4 = ((const int4*)ei)[i];
        int4 d4 = ((const int4*)(ei + NE))[i];
        int p;
        p = atomicAdd(&g_cursor[d4.x], 1); g_csrsrc[p] = s4.x;
        p = atomicAdd(&g_cursor[d4.y], 1); g_csrsrc[p] = s4.y;
        p = atomicAdd(&g_cursor[d4.z], 1); g_csrsrc[p] = s4.z;
        p = atomicAdd(&g_cursor[d4.w], 1); g_csrsrc[p] = s4.w;
    }
    for (int n = gt; n < NN; n += GT) {
        int p = atomicAdd(&g_cursor[n], 1);
        g_csrsrc[p] = n;
    }
}

// ======================= 3xTF32 mma.sync GEMM ================================
#define APAD 36
#define SM_AH 0
#define SM_AL (128 * APAD)
#define SM_WH (SM_AL + 128 * APAD)
#define SM_WL (SM_WH + 64 * APAD)
#define GEMM_SMEM_WORDS (SM_WL + 64 * APAD)   // 13824 words = 55296 B

__device__ __forceinline__ void split_tf32(float x, uint32_t& hi, uint32_t& lo) {
    asm("cvt.rna.tf32.f32 %0, %1;" : "=r"(hi) : "f"(x));
    float l = x - __uint_as_float(hi);
    asm("cvt.rna.tf32.f32 %0, %1;" : "=r"(lo) : "f"(l));
}

#define MMA_TF32(d, a0, a1, a2, a3, b0, b1)                                   \
    asm volatile(                                                             \
        "mma.sync.aligned.m16n8k8.row.col.f32.tf32.tf32.f32 "                 \
        "{%0,%1,%2,%3}, {%4,%5,%6,%7}, {%8,%9}, {%0,%1,%2,%3};"               \
        : "+f"((d)[0]), "+f"((d)[1]), "+f"((d)[2]), "+f"((d)[3])              \
        : "r"(a0), "r"(a1), "r"(a2), "r"(a3), "r"(b0), "r"(b1))

__global__ __launch_bounds__(256) void gemm_mma_kernel(
    const float* __restrict__ Aext, int use_internal,
    const float* __restrict__ Wl, const float* __restrict__ Wr,
    const float* __restrict__ Rw, int M, int K) {
    extern __shared__ uint32_t smu[];

    int z = blockIdx.z;
    const float* __restrict__ W = (z == 0) ? Wl : (z == 1) ? Wr : Rw;
    float* __restrict__ C = (z == 0) ? g_xl : (z == 1) ? g_xr : g_res;
    const float* __restrict__ A = use_internal ? (const float*)g_xcur : Aext;

    int tid = threadIdx.x;
    int warp = tid >> 5;
    int lane = tid & 31;
    int gid = lane >> 2;
    int tig = lane & 3;
    int rowBase = blockIdx.x * 128;

    float acc[8][4];
#pragma unroll
    for (int nt = 0; nt < 8; nt++)
#pragma unroll
        for (int j = 0; j < 4; j++) acc[nt][j] = 0.f;

    for (int k0 = 0; k0 < K; k0 += 32) {
#pragma unroll
        for (int p = 0; p < 4; p++) {
            int lin = tid + p * 256;
            int r = lin >> 3;
            int c = lin & 7;
            int row = rowBase + r;
            float4 f = make_float4(0.f, 0.f, 0.f, 0.f);
            if (row < M) f = *(const float4*)&A[(long)row * K + k0 + c * 4];
            uint4 h, l;
            split_tf32(f.x, h.x, l.x);
            split_tf32(f.y, h.y, l.y);
            split_tf32(f.z, h.z, l.z);
            split_tf32(f.w, h.w, l.w);
            *(uint4*)&smu[SM_AH + r * APAD + c * 4] = h;
            *(uint4*)&smu[SM_AL + r * APAD + c * 4] = l;
        }
#pragma unroll
        for (int p = 0; p < 2; p++) {
            int lin = tid + p * 256;
            int n = lin >> 3;
            int c = lin & 7;
            float4 f = *(const float4*)&W[n * K + k0 + c * 4];
            uint4 h, l;
            split_tf32(f.x, h.x, l.x);
            split_tf32(f.y, h.y, l.y);
            split_tf32(f.z, h.z, l.z);
            split_tf32(f.w, h.w, l.w);
            *(uint4*)&smu[SM_WH + n * APAD + c * 4] = h;
            *(uint4*)&smu[SM_WL + n * APAD + c * 4] = l;
        }
        __syncthreads();

#pragma unroll
        for (int kk = 0; kk < 4; kk++) {
            int kb = kk * 8;
            int r0 = warp * 16 + gid;
            uint32_t ah0 = smu[SM_AH + r0 * APAD + kb + tig];
            uint32_t ah1 = smu[SM_AH + (r0 + 8) * APAD + kb + tig];
            uint32_t ah2 = smu[SM_AH + r0 * APAD + kb + tig + 4];
            uint32_t ah3 = smu[SM_AH + (r0 + 8) * APAD + kb + tig + 4];
            uint32_t al0 = smu[SM_AL + r0 * APAD + kb + tig];
            uint32_t al1 = smu[SM_AL + (r0 + 8) * APAD + kb + tig];
            uint32_t al2 = smu[SM_AL + r0 * APAD + kb + tig + 4];
            uint32_t al3 = smu[SM_AL + (r0 + 8) * APAD + kb + tig + 4];
#pragma unroll
            for (int nt = 0; nt < 8; nt++) {
                int bn = nt * 8 + gid;
                uint32_t bh0 = smu[SM_WH + bn * APAD + kb + tig];
                uint32_t bh1 = smu[SM_WH + bn * APAD + kb + tig + 4];
                uint32_t bl0 = smu[SM_WL + bn * APAD + kb + tig];
                uint32_t bl1 = smu[SM_WL + bn * APAD + kb + tig + 4];
                MMA_TF32(acc[nt], ah0, ah1, ah2, ah3, bh0, bh1);
                MMA_TF32(acc[nt], ah0, ah1, ah2, ah3, bl0, bl1);
                MMA_TF32(acc[nt], al0, al1, al2, al3, bh0, bh1);
            }
        }
        __syncthreads();
    }

    int r0 = rowBase + warp * 16 + gid;
    int r1 = r0 + 8;
#pragma unroll
    for (int nt = 0; nt < 8; nt++) {
        int n0 = nt * 8 + 2 * tig;
        if (r0 < M) *(float2*)&C[(long)r0 * HID + n0] = make_float2(acc[nt][0], acc[nt][1]);
        if (r1 < M) *(float2*)&C[(long)r1 * HID + n0] = make_float2(acc[nt][2], acc[nt][3]);
    }
}

// ---------------- GATv2 aggregation: half-warp per node, degree-sorted ------
// Node = g_perm[halfwarp_id] (degree-sorted) so warp partners and blocks have
// near-equal degrees -> warps retire together -> higher resident occupancy.
//   att·leaky(u) = (0.6·att)·u + (0.4·att)·|u|   (exact for slope 0.2)
__global__ __launch_bounds__(256) void gat_node_kernel(
    const float* __restrict__ att, const float* __restrict__ bia,
    const float* __restrict__ Rb, int relu_flag, int fuse_pool) {
    int gtid = blockIdx.x * blockDim.x + threadIdx.x;
    int hw = gtid >> 4;
    if (hw >= NN) return;
    int n = g_perm[hw];
    int l = threadIdx.x & 15;
    unsigned mask = 0xFFFFu << (threadIdx.x & 16);
    int c0 = l * 4;

    const float4 xrn = *(const float4*)&g_xr[n * HID + c0];
    float4 a6 = *(const float4*)&att[c0];
    float4 a4 = make_float4(0.4f * a6.x, 0.4f * a6.y, 0.4f * a6.z, 0.4f * a6.w);
    a6.x *= 0.6f; a6.y *= 0.6f; a6.z *= 0.6f; a6.w *= 0.6f;

    float den = 0.f;
    float4 acc = make_float4(0.f, 0.f, 0.f, 0.f);

    int e = g_rowptr[n], end = g_rowptr[n + 1];
    for (; e + 1 < end; e += 2) {
        int s0 = g_csrsrc[e];
        int s1 = g_csrsrc[e + 1];
        float4 x0 = *(const float4*)&g_xl[s0 * HID + c0];
        float4 x1 = *(const float4*)&g_xl[s1 * HID + c0];

        float u00 = x0.x + xrn.x, u01 = x0.y + xrn.y;
        float u02 = x0.z + xrn.z, u03 = x0.w + xrn.w;
        float u10 = x1.x + xrn.x, u11 = x1.y + xrn.y;
        float u12 = x1.z + xrn.z, u13 = x1.w + xrn.w;

        float p0 = fmaf(a6.x, u00, fmaf(a6.y, u01, fmaf(a6.z, u02, a6.w * u03)));
        p0 = fmaf(a4.x, fabsf(u00), fmaf(a4.y, fabsf(u01),
             fmaf(a4.z, fabsf(u02), fmaf(a4.w, fabsf(u03), p0))));
        float p1 = fmaf(a6.x, u10, fmaf(a6.y, u11, fmaf(a6.z, u12, a6.w * u13)));
        p1 = fmaf(a4.x, fabsf(u10), fmaf(a4.y, fabsf(u11),
             fmaf(a4.z, fabsf(u12), fmaf(a4.w, fabsf(u13), p1))));

        p0 += __shfl_xor_sync(mask, p0, 1);
        p1 += __shfl_xor_sync(mask, p1, 1);
        p0 += __shfl_xor_sync(mask, p0, 2);
        p1 += __shfl_xor_sync(mask, p1, 2);
        p0 += __shfl_xor_sync(mask, p0, 4);
        p1 += __shfl_xor_sync(mask, p1, 4);
        p0 += __shfl_xor_sync(mask, p0, 8);
        p1 += __shfl_xor_sync(mask, p1, 8);

        float w0 = __expf(p0);
        float w1 = __expf(p1);
        den += w0;
        den += w1;
        acc.x = fmaf(w0, x0.x, acc.x); acc.y = fmaf(w0, x0.y, acc.y);
        acc.z = fmaf(w0, x0.z, acc.z); acc.w = fmaf(w0, x0.w, acc.w);
        acc.x = fmaf(w1, x1.x, acc.x); acc.y = fmaf(w1, x1.y, acc.y);
        acc.z = fmaf(w1, x1.z, acc.z); acc.w = fmaf(w1, x1.w, acc.w);
    }
    if (e < end) {
        int s0 = g_csrsrc[e];
        float4 x0 = *(const float4*)&g_xl[s0 * HID + c0];
        float u00 = x0.x + xrn.x, u01 = x0.y + xrn.y;
        float u02 = x0.z + xrn.z, u03 = x0.w + xrn.w;
        float p0 = fmaf(a6.x, u00, fmaf(a6.y, u01, fmaf(a6.z, u02, a6.w * u03)));
        p0 = fmaf(a4.x, fabsf(u00), fmaf(a4.y, fabsf(u01),
             fmaf(a4.z, fabsf(u02), fmaf(a4.w, fabsf(u03), p0))));
        p0 += __shfl_xor_sync(mask, p0, 1);
        p0 += __shfl_xor_sync(mask, p0, 2);
        p0 += __shfl_xor_sync(mask, p0, 4);
        p0 += __shfl_xor_sync(mask, p0, 8);
        float w0 = __expf(p0);
        den += w0;
        acc.x = fmaf(w0, x0.x, acc.x); acc.y = fmaf(w0, x0.y, acc.y);
        acc.z = fmaf(w0, x0.z, acc.z); acc.w = fmaf(w0, x0.w, acc.w);
    }

    float inv = 1.f / den;   // self-loop guarantees den > 0
    float4 r4 = *(const float4*)&g_res[n * HID + c0];
    float4 b4 = *(const float4*)&bia[c0];
    float4 rb4 = *(const float4*)&Rb[c0];
    float h0 = acc.x * inv + b4.x + r4.x + rb4.x;
    float h1 = acc.y * inv + b4.y + r4.y + rb4.y;
    float h2 = acc.z * inv + b4.z + r4.z + rb4.z;
    float h3 = acc.w * inv + b4.w + r4.w + rb4.w;
    if (relu_flag) {
        h0 = fmaxf(h0, 0.f); h1 = fmaxf(h1, 0.f);
        h2 = fmaxf(h2, 0.f); h3 = fmaxf(h3, 0.f);
    }
    if (!fuse_pool) {
        *(float4*)&g_xcur[n * HID + c0] = make_float4(h0, h1, h2, h3);
    } else {
        int g = g_batch[n];
        atomicAdd(&g_sums[g * HID + c0 + 0], h0);
        atomicAdd(&g_sums[g * HID + c0 + 1], h1);
        atomicAdd(&g_sums[g * HID + c0 + 2], h2);
        atomicAdd(&g_sums[g * HID + c0 + 3], h3);
        if (l == 0) atomicAdd(&g_cntg[g], 1.f);
    }
}

// ---------------- final: mean pool division + linear head -------------------
__global__ void final_kernel(const float* __restrict__ Wf,
                             const float* __restrict__ bf,
                             float* __restrict__ out) {
    int g = blockIdx.x * blockDim.x + threadIdx.x;
    if (g >= NG) return;
    float acc = 0.f;
#pragma unroll
    for (int c = 0; c < HID; c++) acc += g_sums[g * HID + c] * Wf[c];
    float cnt = fmaxf(g_cntg[g], 1.f);
    out[g] = acc / cnt + bf[0];
}

// --------- static stream/event for prep/GEMM overlap (created pre-baseline) -
namespace {
cudaStream_t s_prep = nullptr;
cudaEvent_t  s_evFork = nullptr, s_evJoin = nullptr;
struct ModulePreload {
    ModulePreload() {
        float z = 0.f;
        (void)cudaMemcpyToSymbol(g_cntg, &z, sizeof(float));
        (void)cudaFuncSetAttribute(gemm_mma_kernel,
                                   cudaFuncAttributeMaxDynamicSharedMemorySize,
                                   GEMM_SMEM_WORDS * 4);
        (void)cudaStreamCreateWithFlags(&s_prep, cudaStreamNonBlocking);
        (void)cudaEventCreateWithFlags(&s_evFork, cudaEventDisableTiming);
        (void)cudaEventCreateWithFlags(&s_evJoin, cudaEventDisableTiming);
        (void)cudaDeviceSynchronize();
    }
};
static ModulePreload s_preload;
}

// ---------------- host driver -----------------------------------------------
extern "C" void kernel_launch(void* const* d_in, const int* in_sizes, int n_in,
                              void* d_out, int out_size) {
    const float* x  = (const float*)d_in[0];
    const int*   ei = (const int*)d_in[1];
    const int*   ba = (const int*)d_in[2];
    const float* Wl0 = (const float*)d_in[3];
    const float* Wr0 = (const float*)d_in[4];
    const float* at0 = (const float*)d_in[5];
    const float* b0  = (const float*)d_in[6];
    const float* Rw0 = (const float*)d_in[7];
    const float* Rb0 = (const float*)d_in[8];
    const float* Wl1 = (const float*)d_in[9];
    const float* Wr1 = (const float*)d_in[10];
    const float* at1 = (const float*)d_in[11];
    const float* b1  = (const float*)d_in[12];
    const float* Rw1 = (const float*)d_in[13];
    const float* Rb1 = (const float*)d_in[14];
    const float* Wl2 = (const float*)d_in[15];
    const float* Wr2 = (const float*)d_in[16];
    const float* at2 = (const float*)d_in[17];
    const float* b2  = (const float*)d_in[18];
    const float* Rw2 = (const float*)d_in[19];
    const float* Rb2 = (const float*)d_in[20];
    const float* Wf  = (const float*)d_in[21];
    const float* bf  = (const float*)d_in[22];
    float* out = (float*)d_out;

    dim3 ggrid((NN + 127) / 128, 1, 3);
    dim3 ngrid((NN * 16 + 255) / 256);
    size_t gsm = GEMM_SMEM_WORDS * 4;

    // fork: CSR build + degree sort on s_prep, overlapping layer-0 GEMM.
    cudaEventRecord(s_evFork, 0);
    cudaStreamWaitEvent(s_prep, s_evFork, 0);
    init_kernel<<<(NG * HID + 255) / 256, 256, 0, s_prep>>>();        // #0
    csr_kernel<<<CSRB, 1024, 0, s_prep>>>(ei, ba);                    // #1
    cudaEventRecord(s_evJoin, s_prep);

    gemm_mma_kernel<<<ggrid, 256, gsm>>>(x, 0, Wl0, Wr0, Rw0, NN, 128);  // #2
    cudaStreamWaitEvent(0, s_evJoin, 0);
    gat_node_kernel<<<ngrid, 256>>>(at0, b0, Rb0, 1, 0);              // #3

    gemm_mma_kernel<<<ggrid, 256, gsm>>>(nullptr, 1, Wl1, Wr1, Rw1, NN, 64);  // #4
    gat_node_kernel<<<ngrid, 256>>>(at1, b1, Rb1, 1, 0);              // #5 <- profiled

    gemm_mma_kernel<<<ggrid, 256, gsm>>>(nullptr, 1, Wl2, Wr2, Rw2, NN, 64);
    gat_node_kernel<<<ngrid, 256>>>(at2, b2, Rb2, 0, 1);

    final_kernel<<<1, 256>>>(Wf, bf, out);
}

// round 17
// speedup vs baseline: 1.1985x; 1.0032x over previous
#include <cuda_runtime.h>
#include <cuda_bf16.h>
#include <float.h>
#include <stdint.h>

#define NN 50000
#define NE 1000000
#define ET (NN + NE)
#define HID 64
#define NG 256
#define CSRB 49            // csr blocks (49*1024 >= NN), all co-resident

// ---------------- scratch (static device globals; no runtime allocation) ----
__device__ int   g_cnt[NN];
__device__ int   g_rowptr[NN + 1];
__device__ int   g_cursor[NN];
__device__ int   g_bsum[64];
__device__ int   g_barcnt[8];
__device__ int   g_dhist[256];
__device__ int   g_doff[256];
__device__ int   g_perm[NN];
__device__ int   g_csrsrc[ET];
__device__ int   g_batch[NN];
__device__ float g_xl[NN * HID];
__device__ float g_xr[NN * HID];
__device__ float g_res[NN * HID];
__device__ float g_xcur[NN * HID];
__device__ float g_sums[NG * HID];
__device__ float g_cntg[NG];

// ---------------- init: zero barrier counters + pool accumulators -----------
__global__ void init_kernel() {
    int i = blockIdx.x * blockDim.x + threadIdx.x;
    if (i < NG * HID) g_sums[i] = 0.f;
    if (i < NG) g_cntg[i] = 0.f;
    if (i < 8) g_barcnt[i] = 0;
    if (i < 256) g_dhist[i] = 0;
}

// ---------------- fused CSR build + degree sort, 1 kernel --------------------
__device__ __forceinline__ void gbar(int k) {
    __syncthreads();
    if (threadIdx.x == 0) {
        __threadfence();
        atomicAdd(&g_barcnt[k], 1);
        while (((volatile int*)g_barcnt)[k] < CSRB) __nanosleep(64);
    }
    __syncthreads();
    __threadfence();
}

__global__ __launch_bounds__(1024) void csr_kernel(const int* __restrict__ ei,
                                                   const int* __restrict__ batch) {
    int b = blockIdx.x, t = threadIdx.x;
    int gt = b * 1024 + t;
    const int GT = CSRB * 1024;

    for (int i = gt; i < NN; i += GT) {
        g_cnt[i] = 1;
        g_batch[i] = batch[i];
    }
    gbar(0);

    for (int i = gt; i < NE / 4; i += GT) {
        int4 d4 = ((const int4*)(ei + NE))[i];
        atomicAdd(&g_cnt[d4.x], 1);
        atomicAdd(&g_cnt[d4.y], 1);
        atomicAdd(&g_cnt[d4.z], 1);
        atomicAdd(&g_cnt[d4.w], 1);
    }
    gbar(1);

    {
        int idx = gt;
        int lane = t & 31, w = t >> 5;
        int c = (idx < NN) ? g_cnt[idx] : 0;
        int v = c;
#pragma unroll
        for (int o = 1; o < 32; o <<= 1) {
            int u = __shfl_up_sync(0xffffffffu, v, o);
            if (lane >= o) v += u;
        }
        __shared__ int ws[32];
        __shared__ int s_boff;
        if (lane == 31) ws[w] = v;
        __syncthreads();
        if (w == 0) {
            int s = ws[lane];
#pragma unroll
            for (int o = 1; o < 32; o <<= 1) {
                int u = __shfl_up_sync(0xffffffffu, s, o);
                if (lane >= o) s += u;
            }
            ws[lane] = s;
        }
        __syncthreads();
        int incl = v + (w > 0 ? ws[w - 1] : 0);
        if (t == 1023) g_bsum[b] = incl;
        gbar(2);
        if (w == 0) {
            int acc = 0;
            int i0 = lane, i1 = lane + 32;
            if (i0 < b) acc += g_bsum[i0];
            if (i1 < b) acc += g_bsum[i1];
#pragma unroll
            for (int o = 16; o; o >>= 1) acc += __shfl_xor_sync(0xffffffffu, acc, o);
            if (lane == 0) s_boff = acc;
        }
        __syncthreads();
        int boff = s_boff;
        if (idx < NN) {
            int r = incl - c + boff;
            g_rowptr[idx] = r;
            g_cursor[idx] = r;
            atomicAdd(&g_dhist[c < 255 ? c : 255], 1);
        }
        if (gt == 0) g_rowptr[NN] = ET;
    }
    gbar(3);

    if (b == 0 && t < 32) {
        int base = t * 8;
        int v[8];
        int tot = 0;
#pragma unroll
        for (int j = 0; j < 8; j++) { v[j] = tot; tot += g_dhist[base + j]; }
        int incl = tot;
#pragma unroll
        for (int o = 1; o < 32; o <<= 1) {
            int u = __shfl_up_sync(0xffffffffu, incl, o);
            if (t >= o) incl += u;
        }
        int lane_excl = incl - tot;
#pragma unroll
        for (int j = 0; j < 8; j++) g_doff[base + j] = lane_excl + v[j];
    }
    gbar(4);

    for (int i = gt; i < NN; i += GT) {
        int d = g_cnt[i]; d = d < 255 ? d : 255;
        int pos = atomicAdd(&g_doff[d], 1);
        g_perm[pos] = i;
    }

    for (int i = gt; i < NE / 4; i += GT) {
        int4 s4 = ((const int4*)ei)[i];
        int4 d4 = ((const int4*)(ei + NE))[i];
        int p;
        p = atomicAdd(&g_cursor[d4.x], 1); g_csrsrc[p] = s4.x;
        p = atomicAdd(&g_cursor[d4.y], 1); g_csrsrc[p] = s4.y;
        p = atomicAdd(&g_cursor[d4.z], 1); g_csrsrc[p] = s4.z;
        p = atomicAdd(&g_cursor[d4.w], 1); g_csrsrc[p] = s4.w;
    }
    for (int n = gt; n < NN; n += GT) {
        int p = atomicAdd(&g_cursor[n], 1);
        g_csrsrc[p] = n;
    }
}

// ======================= 3xTF32 mma.sync GEMM ================================
#define APAD 36
#define SM_AH 0
#define SM_AL (128 * APAD)
#define SM_WH (SM_AL + 128 * APAD)
#define SM_WL (SM_WH + 64 * APAD)
#define GEMM_SMEM_WORDS (SM_WL + 64 * APAD)   // 13824 words = 55296 B

__device__ __forceinline__ void split_tf32(float x, uint32_t& hi, uint32_t& lo) {
    asm("cvt.rna.tf32.f32 %0, %1;" : "=r"(hi) : "f"(x));
    float l = x - __uint_as_float(hi);
    asm("cvt.rna.tf32.f32 %0, %1;" : "=r"(lo) : "f"(l));
}

#define MMA_TF32(d, a0, a1, a2, a3, b0, b1)                                   \
    asm volatile(                                                             \
        "mma.sync.aligned.m16n8k8.row.col.f32.tf32.tf32.f32 "                 \
        "{%0,%1,%2,%3}, {%4,%5,%6,%7}, {%8,%9}, {%0,%1,%2,%3};"               \
        : "+f"((d)[0]), "+f"((d)[1]), "+f"((d)[2]), "+f"((d)[3])              \
        : "r"(a0), "r"(a1), "r"(a2), "r"(a3), "r"(b0), "r"(b1))

__global__ __launch_bounds__(256) void gemm_mma_kernel(
    const float* __restrict__ Aext, int use_internal,
    const float* __restrict__ Wl, const float* __restrict__ Wr,
    const float* __restrict__ Rw, int M, int K) {
    extern __shared__ uint32_t smu[];

    int z = blockIdx.z;
    const float* __restrict__ W = (z == 0) ? Wl : (z == 1) ? Wr : Rw;
    float* __restrict__ C = (z == 0) ? g_xl : (z == 1) ? g_xr : g_res;
    const float* __restrict__ A = use_internal ? (const float*)g_xcur : Aext;

    int tid = threadIdx.x;
    int warp = tid >> 5;
    int lane = tid & 31;
    int gid = lane >> 2;
    int tig = lane & 3;
    int rowBase = blockIdx.x * 128;

    float acc[8][4];
#pragma unroll
    for (int nt = 0; nt < 8; nt++)
#pragma unroll
        for (int j = 0; j < 4; j++) acc[nt][j] = 0.f;

    for (int k0 = 0; k0 < K; k0 += 32) {
#pragma unroll
        for (int p = 0; p < 4; p++) {
            int lin = tid + p * 256;
            int r = lin >> 3;
            int c = lin & 7;
            int row = rowBase + r;
            float4 f = make_float4(0.f, 0.f, 0.f, 0.f);
            if (row < M) f = *(const float4*)&A[(long)row * K + k0 + c * 4];
            uint4 h, l;
            split_tf32(f.x, h.x, l.x);
            split_tf32(f.y, h.y, l.y);
            split_tf32(f.z, h.z, l.z);
            split_tf32(f.w, h.w, l.w);
            *(uint4*)&smu[SM_AH + r * APAD + c * 4] = h;
            *(uint4*)&smu[SM_AL + r * APAD + c * 4] = l;
        }
#pragma unroll
        for (int p = 0; p < 2; p++) {
            int lin = tid + p * 256;
            int n = lin >> 3;
            int c = lin & 7;
            float4 f = *(const float4*)&W[n * K + k0 + c * 4];
            uint4 h, l;
            split_tf32(f.x, h.x, l.x);
            split_tf32(f.y, h.y, l.y);
            split_tf32(f.z, h.z, l.z);
            split_tf32(f.w, h.w, l.w);
            *(uint4*)&smu[SM_WH + n * APAD + c * 4] = h;
            *(uint4*)&smu[SM_WL + n * APAD + c * 4] = l;
        }
        __syncthreads();

#pragma unroll
        for (int kk = 0; kk < 4; kk++) {
            int kb = kk * 8;
            int r0 = warp * 16 + gid;
            uint32_t ah0 = smu[SM_AH + r0 * APAD + kb + tig];
            uint32_t ah1 = smu[SM_AH + (r0 + 8) * APAD + kb + tig];
            uint32_t ah2 = smu[SM_AH + r0 * APAD + kb + tig + 4];
            uint32_t ah3 = smu[SM_AH + (r0 + 8) * APAD + kb + tig + 4];
            uint32_t al0 = smu[SM_AL + r0 * APAD + kb + tig];
            uint32_t al1 = smu[SM_AL + (r0 + 8) * APAD + kb + tig];
            uint32_t al2 = smu[SM_AL + r0 * APAD + kb + tig + 4];
            uint32_t al3 = smu[SM_AL + (r0 + 8) * APAD + kb + tig + 4];
#pragma unroll
            for (int nt = 0; nt < 8; nt++) {
                int bn = nt * 8 + gid;
                uint32_t bh0 = smu[SM_WH + bn * APAD + kb + tig];
                uint32_t bh1 = smu[SM_WH + bn * APAD + kb + tig + 4];
                uint32_t bl0 = smu[SM_WL + bn * APAD + kb + tig];
                uint32_t bl1 = smu[SM_WL + bn * APAD + kb + tig + 4];
                MMA_TF32(acc[nt], ah0, ah1, ah2, ah3, bh0, bh1);
                MMA_TF32(acc[nt], ah0, ah1, ah2, ah3, bl0, bl1);
                MMA_TF32(acc[nt], al0, al1, al2, al3, bh0, bh1);
            }
        }
        __syncthreads();
    }

    int r0 = rowBase + warp * 16 + gid;
    int r1 = r0 + 8;
#pragma unroll
    for (int nt = 0; nt < 8; nt++) {
        int n0 = nt * 8 + 2 * tig;
        if (r0 < M) *(float2*)&C[(long)r0 * HID + n0] = make_float2(acc[nt][0], acc[nt][1]);
        if (r1 < M) *(float2*)&C[(long)r1 * HID + n0] = make_float2(acc[nt][2], acc[nt][3]);
    }
}

// ---------------- GATv2 aggregation: half-warp/node, 4-edge unroll ----------
//   att·leaky(u) = (0.6·att)·u + (0.4·att)·|u|   (exact for slope 0.2)
// 4 independent gather->dot->shuffle->exp chains per iteration hide the
// ~26cyc/step SHFL latency (issue-limiter per R16 ncu).
__device__ __forceinline__ float edge_logit(
    float4 x, float4 xrn, float4 a6, float4 a4) {
    float u0 = x.x + xrn.x, u1 = x.y + xrn.y;
    float u2 = x.z + xrn.z, u3 = x.w + xrn.w;
    float p = fmaf(a6.x, u0, fmaf(a6.y, u1, fmaf(a6.z, u2, a6.w * u3)));
    return fmaf(a4.x, fabsf(u0), fmaf(a4.y, fabsf(u1),
           fmaf(a4.z, fabsf(u2), fmaf(a4.w, fabsf(u3), p))));
}

__global__ __launch_bounds__(256) void gat_node_kernel(
    const float* __restrict__ att, const float* __restrict__ bia,
    const float* __restrict__ Rb, int relu_flag, int fuse_pool) {
    int gtid = blockIdx.x * blockDim.x + threadIdx.x;
    int hw = gtid >> 4;
    if (hw >= NN) return;
    int n = g_perm[hw];
    int l = threadIdx.x & 15;
    unsigned mask = 0xFFFFu << (threadIdx.x & 16);
    int c0 = l * 4;

    const float4 xrn = *(const float4*)&g_xr[n * HID + c0];
    float4 a6 = *(const float4*)&att[c0];
    float4 a4 = make_float4(0.4f * a6.x, 0.4f * a6.y, 0.4f * a6.z, 0.4f * a6.w);
    a6.x *= 0.6f; a6.y *= 0.6f; a6.z *= 0.6f; a6.w *= 0.6f;

    float den = 0.f;
    float4 acc = make_float4(0.f, 0.f, 0.f, 0.f);

    int e = g_rowptr[n], end = g_rowptr[n + 1];
    for (; e + 3 < end; e += 4) {
        int s0 = g_csrsrc[e];
        int s1 = g_csrsrc[e + 1];
        int s2 = g_csrsrc[e + 2];
        int s3 = g_csrsrc[e + 3];
        float4 x0 = *(const float4*)&g_xl[s0 * HID + c0];
        float4 x1 = *(const float4*)&g_xl[s1 * HID + c0];
        float4 x2 = *(const float4*)&g_xl[s2 * HID + c0];
        float4 x3 = *(const float4*)&g_xl[s3 * HID + c0];

        float p0 = edge_logit(x0, xrn, a6, a4);
        float p1 = edge_logit(x1, xrn, a6, a4);
        float p2 = edge_logit(x2, xrn, a6, a4);
        float p3 = edge_logit(x3, xrn, a6, a4);

        p0 += __shfl_xor_sync(mask, p0, 1);
        p1 += __shfl_xor_sync(mask, p1, 1);
        p2 += __shfl_xor_sync(mask, p2, 1);
        p3 += __shfl_xor_sync(mask, p3, 1);
        p0 += __shfl_xor_sync(mask, p0, 2);
        p1 += __shfl_xor_sync(mask, p1, 2);
        p2 += __shfl_xor_sync(mask, p2, 2);
        p3 += __shfl_xor_sync(mask, p3, 2);
        p0 += __shfl_xor_sync(mask, p0, 4);
        p1 += __shfl_xor_sync(mask, p1, 4);
        p2 += __shfl_xor_sync(mask, p2, 4);
        p3 += __shfl_xor_sync(mask, p3, 4);
        p0 += __shfl_xor_sync(mask, p0, 8);
        p1 += __shfl_xor_sync(mask, p1, 8);
        p2 += __shfl_xor_sync(mask, p2, 8);
        p3 += __shfl_xor_sync(mask, p3, 8);

        float w0 = __expf(p0);
        float w1 = __expf(p1);
        float w2 = __expf(p2);
        float w3 = __expf(p3);
        den += w0; den += w1; den += w2; den += w3;
        acc.x = fmaf(w0, x0.x, acc.x); acc.y = fmaf(w0, x0.y, acc.y);
        acc.z = fmaf(w0, x0.z, acc.z); acc.w = fmaf(w0, x0.w, acc.w);
        acc.x = fmaf(w1, x1.x, acc.x); acc.y = fmaf(w1, x1.y, acc.y);
        acc.z = fmaf(w1, x1.z, acc.z); acc.w = fmaf(w1, x1.w, acc.w);
        acc.x = fmaf(w2, x2.x, acc.x); acc.y = fmaf(w2, x2.y, acc.y);
        acc.z = fmaf(w2, x2.z, acc.z); acc.w = fmaf(w2, x2.w, acc.w);
        acc.x = fmaf(w3, x3.x, acc.x); acc.y = fmaf(w3, x3.y, acc.y);
        acc.z = fmaf(w3, x3.z, acc.z); acc.w = fmaf(w3, x3.w, acc.w);
    }
    for (; e < end; e++) {
        int s0 = g_csrsrc[e];
        float4 x0 = *(const float4*)&g_xl[s0 * HID + c0];
        float p0 = edge_logit(x0, xrn, a6, a4);
        p0 += __shfl_xor_sync(mask, p0, 1);
        p0 += __shfl_xor_sync(mask, p0, 2);
        p0 += __shfl_xor_sync(mask, p0, 4);
        p0 += __shfl_xor_sync(mask, p0, 8);
        float w0 = __expf(p0);
        den += w0;
        acc.x = fmaf(w0, x0.x, acc.x); acc.y = fmaf(w0, x0.y, acc.y);
        acc.z = fmaf(w0, x0.z, acc.z); acc.w = fmaf(w0, x0.w, acc.w);
    }

    float inv = 1.f / den;   // self-loop guarantees den > 0
    float4 r4 = *(const float4*)&g_res[n * HID + c0];
    float4 b4 = *(const float4*)&bia[c0];
    float4 rb4 = *(const float4*)&Rb[c0];
    float h0 = acc.x * inv + b4.x + r4.x + rb4.x;
    float h1 = acc.y * inv + b4.y + r4.y + rb4.y;
    float h2 = acc.z * inv + b4.z + r4.z + rb4.z;
    float h3 = acc.w * inv + b4.w + r4.w + rb4.w;
    if (relu_flag) {
        h0 = fmaxf(h0, 0.f); h1 = fmaxf(h1, 0.f);
        h2 = fmaxf(h2, 0.f); h3 = fmaxf(h3, 0.f);
    }
    if (!fuse_pool) {
        *(float4*)&g_xcur[n * HID + c0] = make_float4(h0, h1, h2, h3);
    } else {
        int g = g_batch[n];
        atomicAdd(&g_sums[g * HID + c0 + 0], h0);
        atomicAdd(&g_sums[g * HID + c0 + 1], h1);
        atomicAdd(&g_sums[g * HID + c0 + 2], h2);
        atomicAdd(&g_sums[g * HID + c0 + 3], h3);
        if (l == 0) atomicAdd(&g_cntg[g], 1.f);
    }
}

// ---------------- final: mean pool division + linear head -------------------
__global__ void final_kernel(const float* __restrict__ Wf,
                             const float* __restrict__ bf,
                             float* __restrict__ out) {
    int g = blockIdx.x * blockDim.x + threadIdx.x;
    if (g >= NG) return;
    float acc = 0.f;
#pragma unroll
    for (int c = 0; c < HID; c++) acc += g_sums[g * HID + c] * Wf[c];
    float cnt = fmaxf(g_cntg[g], 1.f);
    out[g] = acc / cnt + bf[0];
}

// --------- static stream/event for prep/GEMM overlap (created pre-baseline) -
namespace {
cudaStream_t s_prep = nullptr;
cudaEvent_t  s_evFork = nullptr, s_evJoin = nullptr;
struct ModulePreload {
    ModulePreload() {
        float z = 0.f;
        (void)cudaMemcpyToSymbol(g_cntg, &z, sizeof(float));
        (void)cudaFuncSetAttribute(gemm_mma_kernel,
                                   cudaFuncAttributeMaxDynamicSharedMemorySize,
                                   GEMM_SMEM_WORDS * 4);
        (void)cudaStreamCreateWithFlags(&s_prep, cudaStreamNonBlocking);
        (void)cudaEventCreateWithFlags(&s_evFork, cudaEventDisableTiming);
        (void)cudaEventCreateWithFlags(&s_evJoin, cudaEventDisableTiming);
        (void)cudaDeviceSynchronize();
    }
};
static ModulePreload s_preload;
}

// ---------------- host driver -----------------------------------------------
extern "C" void kernel_launch(void* const* d_in, const int* in_sizes, int n_in,
                              void* d_out, int out_size) {
    const float* x  = (const float*)d_in[0];
    const int*   ei = (const int*)d_in[1];
    const int*   ba = (const int*)d_in[2];
    const float* Wl0 = (const float*)d_in[3];
    const float* Wr0 = (const float*)d_in[4];
    const float* at0 = (const float*)d_in[5];
    const float* b0  = (const float*)d_in[6];
    const float* Rw0 = (const float*)d_in[7];
    const float* Rb0 = (const float*)d_in[8];
    const float* Wl1 = (const float*)d_in[9];
    const float* Wr1 = (const float*)d_in[10];
    const float* at1 = (const float*)d_in[11];
    const float* b1  = (const float*)d_in[12];
    const float* Rw1 = (const float*)d_in[13];
    const float* Rb1 = (const float*)d_in[14];
    const float* Wl2 = (const float*)d_in[15];
    const float* Wr2 = (const float*)d_in[16];
    const float* at2 = (const float*)d_in[17];
    const float* b2  = (const float*)d_in[18];
    const float* Rw2 = (const float*)d_in[19];
    const float* Rb2 = (const float*)d_in[20];
    const float* Wf  = (const float*)d_in[21];
    const float* bf  = (const float*)d_in[22];
    float* out = (float*)d_out;

    dim3 ggrid((NN + 127) / 128, 1, 3);
    dim3 ngrid((NN * 16 + 255) / 256);
    size_t gsm = GEMM_SMEM_WORDS * 4;

    cudaEventRecord(s_evFork, 0);
    cudaStreamWaitEvent(s_prep, s_evFork, 0);
    init_kernel<<<(NG * HID + 255) / 256, 256, 0, s_prep>>>();        // #0
    csr_kernel<<<CSRB, 1024, 0, s_prep>>>(ei, ba);                    // #1
    cudaEventRecord(s_evJoin, s_prep);

    gemm_mma_kernel<<<ggrid, 256, gsm>>>(x, 0, Wl0, Wr0, Rw0, NN, 128);  // #2
    cudaStreamWaitEvent(0, s_evJoin, 0);
    gat_node_kernel<<<ngrid, 256>>>(at0, b0, Rb0, 1, 0);              // #3

    gemm_mma_kernel<<<ggrid, 256, gsm>>>(nullptr, 1, Wl1, Wr1, Rw1, NN, 64);  // #4
    gat_node_kernel<<<ngrid, 256>>>(at1, b1, Rb1, 1, 0);              // #5 <- profiled

    gemm_mma_kernel<<<ggrid, 256, gsm>>>(nullptr, 1, Wl2, Wr2, Rw2, NN, 64);
    gat_node_kernel<<<ngrid, 256>>>(at2, b2, Rb2, 0, 1);

    final_kernel<<<1, 256>>>(Wf, bf, out);
}